// round 2
// baseline (speedup 1.0000x reference)
#include <cuda_runtime.h>
#include <math.h>

// ---------------------------------------------------------------------------
// Problem constants (fixed shapes from reference setup_inputs)
// ---------------------------------------------------------------------------
#define BB 2
#define TT 4096
#define DD 1024
#define FF 4096
#define SS 4096
#define BT (BB * TT)          // 8192
#define BTD ((size_t)BT * DD) // 8,388,608
#define BTF ((size_t)BT * FF) // 33,554,432
#define NC 64                 // scan chunks
#define CH 64                 // chunk length (NC*CH == TT)
#define BDNC ((size_t)BB * DD * NC) // 131072

// Scratch layout in one big __device__ array (allocated at module load — legal)
__device__ float g_scratch[4 * BTD + 2 * BTF + 3 * BDNC + 4 * (size_t)BT];

#define OFF_XN   ((size_t)0)
#define OFF_CONV (OFF_XN + BTD)          // also reused as q
#define OFF_Z    (OFF_CONV + BTD)        // also reused as retrieved
#define OFF_HT   (OFF_Z + BTD)
#define OFF_BIG1 (OFF_HT + BTD)          // scores / gate preact
#define OFF_BIG2 (OFF_BIG1 + BTF)        // silu(gate)*up
#define OFF_SA   (OFF_BIG2 + BTF)
#define OFF_SB   (OFF_SA + BDNC)
#define OFF_HS   (OFF_SB + BDNC)
#define OFF_TV   (OFF_HS + BDNC)
#define OFF_TI   (OFF_TV + (size_t)BT * 2)

// ---------------------------------------------------------------------------
// RMSNorm: one block per row of D=1024, 256 threads * float4
// ---------------------------------------------------------------------------
__global__ void __launch_bounds__(256) rmsnorm_kernel(
    const float* __restrict__ x, const float* __restrict__ w,
    float* __restrict__ out)
{
    const size_t row = blockIdx.x;
    const int tid = threadIdx.x;
    const float4* xr = (const float4*)(x + row * DD);
    float4 a = xr[tid];
    float ss = a.x * a.x + a.y * a.y + a.z * a.z + a.w * a.w;
    #pragma unroll
    for (int o = 16; o; o >>= 1) ss += __shfl_xor_sync(0xffffffffu, ss, o);
    __shared__ float wss[8];
    if ((tid & 31) == 0) wss[tid >> 5] = ss;
    __syncthreads();
    if (tid < 8) {
        float v = wss[tid];
        #pragma unroll
        for (int o = 4; o; o >>= 1) v += __shfl_xor_sync(0xffu, v, o);
        if (tid == 0) wss[0] = v;
    }
    __syncthreads();
    const float inv = rsqrtf(wss[0] * (1.0f / DD) + 1e-6f);
    float4 wv = ((const float4*)w)[tid];
    float4 o4;
    o4.x = a.x * wv.x * inv;
    o4.y = a.y * wv.y * inv;
    o4.z = a.z * wv.z * inv;
    o4.w = a.w * wv.w * inv;
    ((float4*)(out + row * DD))[tid] = o4;
}

// ---------------------------------------------------------------------------
// Multi-scale causal depthwise conv (k=3,7,15 summed). One thread per (b,t,d).
// Combined 15-tap window; weights merged per tap.
// ---------------------------------------------------------------------------
__global__ void __launch_bounds__(256) conv_kernel(
    const float* __restrict__ xn,
    const float* __restrict__ w3, const float* __restrict__ w7,
    const float* __restrict__ w15, float* __restrict__ out)
{
    const size_t idx = (size_t)blockIdx.x * blockDim.x + threadIdx.x;
    const int d = (int)(idx & (DD - 1));
    const size_t bt = idx / DD;
    const int t = (int)(bt & (TT - 1));
    const int b = (int)(bt / TT);
    const float* base = xn + (size_t)b * TT * DD + d;
    float acc = 0.0f;
    #pragma unroll
    for (int j = 0; j < 15; j++) {
        int tt = t - 14 + j;
        if (tt < 0) continue;
        float wsum = w15[d * 15 + j];
        if (j >= 8)  wsum += w7[d * 7 + (j - 8)];
        if (j >= 12) wsum += w3[d * 3 + (j - 12)];
        acc += wsum * base[(size_t)tt * DD];
    }
    out[idx] = acc;
}

// ---------------------------------------------------------------------------
// Generic fp32 SGEMM: C[M,N] = epi(A[M,K] @ W[N,K]^T). 128x128x8 tiles,
// 256 threads, 8x8 per thread, double-buffered smem. All dims multiples of 128/8.
// ---------------------------------------------------------------------------
#define EPI_NONE    0
#define EPI_SCALE   1
#define EPI_BIAS    2
#define EPI_SIGBIAS 3
#define EPI_RESID   4
#define EPI_SILUMUL 5

template <int EPI>
__global__ void __launch_bounds__(256, 2) sgemm_kernel(
    const float* __restrict__ A, const float* __restrict__ W,
    float* __restrict__ C, const float* __restrict__ bias,
    const float* __restrict__ extra,
    int M, int N, int K, float scale)
{
    __shared__ float As[2][8][128];
    __shared__ float Bs[2][8][128];
    const int tid = threadIdx.x;
    const int bm = blockIdx.y * 128;
    const int bn = blockIdx.x * 128;
    const int lrow = tid >> 1;
    const int lcol = (tid & 1) << 2;
    const float* Ap = A + (size_t)(bm + lrow) * K + lcol;
    const float* Wp = W + (size_t)(bn + lrow) * K + lcol;
    const int tx = (tid & 15) << 3;
    const int ty = (tid >> 4) << 3;

    float acc[8][8];
    #pragma unroll
    for (int i = 0; i < 8; i++)
        #pragma unroll
        for (int j = 0; j < 8; j++) acc[i][j] = 0.0f;

    float4 a0 = *(const float4*)Ap;
    float4 b0 = *(const float4*)Wp;
    As[0][lcol + 0][lrow] = a0.x; As[0][lcol + 1][lrow] = a0.y;
    As[0][lcol + 2][lrow] = a0.z; As[0][lcol + 3][lrow] = a0.w;
    Bs[0][lcol + 0][lrow] = b0.x; Bs[0][lcol + 1][lrow] = b0.y;
    Bs[0][lcol + 2][lrow] = b0.z; Bs[0][lcol + 3][lrow] = b0.w;
    __syncthreads();

    int buf = 0;
    for (int k0 = 8; k0 <= K; k0 += 8) {
        float4 an, bn4;
        const bool more = (k0 < K);
        if (more) {
            an  = *(const float4*)(Ap + k0);
            bn4 = *(const float4*)(Wp + k0);
        }
        #pragma unroll
        for (int kk = 0; kk < 8; kk++) {
            float af[8], bf[8];
            *(float4*)(af)     = *(const float4*)(&As[buf][kk][ty]);
            *(float4*)(af + 4) = *(const float4*)(&As[buf][kk][ty + 4]);
            *(float4*)(bf)     = *(const float4*)(&Bs[buf][kk][tx]);
            *(float4*)(bf + 4) = *(const float4*)(&Bs[buf][kk][tx + 4]);
            #pragma unroll
            for (int i = 0; i < 8; i++)
                #pragma unroll
                for (int j = 0; j < 8; j++)
                    acc[i][j] = fmaf(af[i], bf[j], acc[i][j]);
        }
        if (more) {
            buf ^= 1;
            As[buf][lcol + 0][lrow] = an.x;  As[buf][lcol + 1][lrow] = an.y;
            As[buf][lcol + 2][lrow] = an.z;  As[buf][lcol + 3][lrow] = an.w;
            Bs[buf][lcol + 0][lrow] = bn4.x; Bs[buf][lcol + 1][lrow] = bn4.y;
            Bs[buf][lcol + 2][lrow] = bn4.z; Bs[buf][lcol + 3][lrow] = bn4.w;
            __syncthreads();
        }
    }

    #pragma unroll
    for (int i = 0; i < 8; i++) {
        const size_t off = (size_t)(bm + ty + i) * N + bn + tx;
        float outv[8];
        #pragma unroll
        for (int j = 0; j < 8; j++) {
            float v = acc[i][j];
            if (EPI == EPI_SCALE) {
                v *= scale;
            } else if (EPI == EPI_BIAS) {
                v += bias[bn + tx + j];
            } else if (EPI == EPI_SIGBIAS) {
                v += bias[bn + tx + j];
                v = 1.0f / (1.0f + expf(-v));
            } else if (EPI == EPI_RESID) {
                v += extra[off + j];
            } else if (EPI == EPI_SILUMUL) {
                const float g = extra[off + j];
                v *= g / (1.0f + expf(-g));
            }
            outv[j] = v;
        }
        *(float4*)(C + off)     = *(const float4*)(outv);
        *(float4*)(C + off + 4) = *(const float4*)(outv + 4);
    }
}

// ---------------------------------------------------------------------------
// MinGRU chunked scan: h_t = (1-z_t) h_{t-1} + z_t ht_t
// Pass 1: per-(b,d,chunk) composite (A,B). Pass 2: per-(b,d) sequential chunk
// combine -> chunk start states + h_last. Pass 3: per-(b,d,chunk) replay,
// writing h into the residual stream (x += h).
// ---------------------------------------------------------------------------
__global__ void __launch_bounds__(256) scan1_kernel(
    const float* __restrict__ z, const float* __restrict__ ht,
    float* __restrict__ Aout, float* __restrict__ Bout)
{
    const int tid = blockIdx.x * blockDim.x + threadIdx.x; // < B*D*NC
    const int d = tid & (DD - 1);
    const int r = tid / DD;
    const int c = r & (NC - 1);
    const int b = r / NC;
    const size_t base = ((size_t)b * TT + (size_t)c * CH) * DD + d;
    float Aa = 1.0f, Bb = 0.0f;
    #pragma unroll 4
    for (int t = 0; t < CH; t++) {
        const float zt = z[base + (size_t)t * DD];
        const float hh = ht[base + (size_t)t * DD];
        const float a = 1.0f - zt;
        Bb = a * Bb + zt * hh;
        Aa *= a;
    }
    Aout[tid] = Aa;
    Bout[tid] = Bb;
}

__global__ void __launch_bounds__(256) scan2_kernel(
    const float* __restrict__ h_prev, const float* __restrict__ Ain,
    const float* __restrict__ Bin, float* __restrict__ hstart,
    float* __restrict__ hlast)
{
    const int tid = blockIdx.x * blockDim.x + threadIdx.x;
    if (tid >= BB * DD) return;
    const int d = tid & (DD - 1);
    const int b = tid / DD;
    float h = h_prev[tid];
    for (int c = 0; c < NC; c++) {
        const size_t i = ((size_t)b * NC + c) * DD + d;
        hstart[i] = h;
        h = Ain[i] * h + Bin[i];
    }
    hlast[tid] = h;
}

__global__ void __launch_bounds__(256) scan3_kernel(
    const float* __restrict__ z, const float* __restrict__ ht,
    const float* __restrict__ hstart, float* __restrict__ xout)
{
    const int tid = blockIdx.x * blockDim.x + threadIdx.x;
    const int d = tid & (DD - 1);
    const int r = tid / DD;
    const int c = r & (NC - 1);
    const int b = r / NC;
    const size_t base = ((size_t)b * TT + (size_t)c * CH) * DD + d;
    float h = hstart[tid];
    for (int t = 0; t < CH; t++) {
        const float zt = z[base + (size_t)t * DD];
        const float hh = ht[base + (size_t)t * DD];
        h = (1.0f - zt) * h + zt * hh;
        xout[base + (size_t)t * DD] += h;
    }
}

// ---------------------------------------------------------------------------
// Top-2 over S=4096 scores per row (block per row). Ties -> lower index
// (matches jax.lax.top_k ordering; ties ~impossible with random floats).
// ---------------------------------------------------------------------------
__device__ __forceinline__ void top2_insert(float v, int i,
    float& v1, int& i1, float& v2, int& i2)
{
    if (v > v1 || (v == v1 && i < i1)) { v2 = v1; i2 = i1; v1 = v; i1 = i; }
    else if (v > v2 || (v == v2 && i < i2)) { v2 = v; i2 = i; }
}

__global__ void __launch_bounds__(256) top2_kernel(
    const float* __restrict__ scores, float* __restrict__ topv,
    int* __restrict__ topi)
{
    const int row = blockIdx.x;
    const int tid = threadIdx.x;
    const float* sr = scores + (size_t)row * SS;
    float v1 = -3.4e38f, v2 = -3.4e38f;
    int i1 = 0x7fffffff, i2 = 0x7fffffff;
    for (int s = tid; s < SS; s += 256)
        top2_insert(sr[s], s, v1, i1, v2, i2);
    __shared__ float sv1[256], sv2[256];
    __shared__ int si1[256], si2[256];
    sv1[tid] = v1; sv2[tid] = v2; si1[tid] = i1; si2[tid] = i2;
    __syncthreads();
    for (int o = 128; o; o >>= 1) {
        if (tid < o) {
            float a1 = sv1[tid], a2 = sv2[tid];
            int b1 = si1[tid], b2 = si2[tid];
            top2_insert(sv1[tid + o], si1[tid + o], a1, b1, a2, b2);
            top2_insert(sv2[tid + o], si2[tid + o], a1, b1, a2, b2);
            sv1[tid] = a1; sv2[tid] = a2; si1[tid] = b1; si2[tid] = b2;
        }
        __syncthreads();
    }
    if (tid == 0) {
        topv[row * 2 + 0] = sv1[0];
        topv[row * 2 + 1] = sv2[0];
        topi[row * 2 + 0] = si1[0];
        topi[row * 2 + 1] = si2[0];
    }
}

// retrieved[row, d] = softmax(top2) . slot_values[ids]
__global__ void __launch_bounds__(256) gather_kernel(
    const float* __restrict__ topv, const int* __restrict__ topi,
    const float* __restrict__ V, float* __restrict__ out)
{
    const size_t idx = (size_t)blockIdx.x * blockDim.x + threadIdx.x;
    const int d = (int)(idx & (DD - 1));
    const size_t row = idx / DD;
    const float v1 = topv[row * 2 + 0];
    const float v2 = topv[row * 2 + 1];
    const int i1 = topi[row * 2 + 0];
    const int i2 = topi[row * 2 + 1];
    const float e = expf(v2 - v1);            // v2 <= v1
    const float inv = 1.0f / (1.0f + e);
    const float w1 = inv, w2 = e * inv;
    out[idx] = w1 * V[(size_t)i1 * DD + d] + w2 * V[(size_t)i2 * DD + d];
}

// ---------------------------------------------------------------------------
// Launch sequence
// ---------------------------------------------------------------------------
extern "C" void kernel_launch(void* const* d_in, const int* in_sizes, int n_in,
                              void* d_out, int out_size)
{
    (void)in_sizes; (void)n_in; (void)out_size;
    const float* x        = (const float*)d_in[0];
    const float* h_prev   = (const float*)d_in[1];
    const float* norm1_w  = (const float*)d_in[2];
    const float* conv3_w  = (const float*)d_in[3];
    const float* conv7_w  = (const float*)d_in[4];
    const float* conv15_w = (const float*)d_in[5];
    const float* mix_w    = (const float*)d_in[6];
    const float* norm2_w  = (const float*)d_in[7];
    const float* Wz_w     = (const float*)d_in[8];
    const float* Wz_b     = (const float*)d_in[9];
    const float* Wh_w     = (const float*)d_in[10];
    const float* Wh_b     = (const float*)d_in[11];
    const float* norm3_w  = (const float*)d_in[12];
    const float* slot_k   = (const float*)d_in[13];
    const float* slot_v   = (const float*)d_in[14];
    const float* projq_w  = (const float*)d_in[15];
    const float* projout_w= (const float*)d_in[16];
    const float* norm4_w  = (const float*)d_in[17];
    const float* gate_w   = (const float*)d_in[18];
    const float* up_w     = (const float*)d_in[19];
    const float* down_w   = (const float*)d_in[20];
    float* out = (float*)d_out;

    float* scr = nullptr;
    cudaGetSymbolAddress((void**)&scr, g_scratch);
    float* xn    = scr + OFF_XN;
    float* conv  = scr + OFF_CONV;   // also q
    float* zbuf  = scr + OFF_Z;      // also retrieved
    float* htbuf = scr + OFF_HT;
    float* big1  = scr + OFF_BIG1;   // scores / gate preact
    float* big2  = scr + OFF_BIG2;
    float* scanA = scr + OFF_SA;
    float* scanB = scr + OFF_SB;
    float* hstart= scr + OFF_HS;
    float* topv  = scr + OFF_TV;
    int*   topi  = (int*)(scr + OFF_TI);

    const dim3 blk(256);
    const dim3 gD(DD / 128, BT / 128);   // N=1024 GEMMs
    const dim3 gF(FF / 128, BT / 128);   // N=4096 GEMMs
    const dim3 gS(SS / 128, BT / 128);   // scores GEMM

    // running x lives in d_out
    cudaMemcpyAsync(out, x, BTD * sizeof(float), cudaMemcpyDeviceToDevice);

    // 1. conv block
    rmsnorm_kernel<<<BT, blk>>>(out, norm1_w, xn);
    conv_kernel<<<(unsigned)(BTD / 256), blk>>>(xn, conv3_w, conv7_w, conv15_w, conv);
    sgemm_kernel<EPI_RESID><<<gD, blk>>>(conv, mix_w, out, nullptr, out, BT, DD, DD, 1.0f);

    // 2. MinGRU
    rmsnorm_kernel<<<BT, blk>>>(out, norm2_w, xn);
    sgemm_kernel<EPI_SIGBIAS><<<gD, blk>>>(xn, Wz_w, zbuf, Wz_b, nullptr, BT, DD, DD, 1.0f);
    sgemm_kernel<EPI_BIAS><<<gD, blk>>>(xn, Wh_w, htbuf, Wh_b, nullptr, BT, DD, DD, 1.0f);
    scan1_kernel<<<(unsigned)(BDNC / 256), blk>>>(zbuf, htbuf, scanA, scanB);
    scan2_kernel<<<(BB * DD + 255) / 256, blk>>>(h_prev, scanA, scanB, hstart, out + BTD);
    scan3_kernel<<<(unsigned)(BDNC / 256), blk>>>(zbuf, htbuf, hstart, out);

    // 3. slot memory, top-2 routing
    rmsnorm_kernel<<<BT, blk>>>(out, norm3_w, xn);
    sgemm_kernel<EPI_NONE><<<gD, blk>>>(xn, projq_w, conv, nullptr, nullptr, BT, DD, DD, 1.0f);
    sgemm_kernel<EPI_SCALE><<<gS, blk>>>(conv, slot_k, big1, nullptr, nullptr, BT, SS, DD, 0.03125f);
    top2_kernel<<<BT, blk>>>(big1, topv, topi);
    gather_kernel<<<(unsigned)(BTD / 256), blk>>>(topv, topi, slot_v, zbuf);
    sgemm_kernel<EPI_RESID><<<gD, blk>>>(zbuf, projout_w, out, nullptr, out, BT, DD, DD, 1.0f);

    // 4. SwiGLU FFN
    rmsnorm_kernel<<<BT, blk>>>(out, norm4_w, xn);
    sgemm_kernel<EPI_NONE><<<gF, blk>>>(xn, gate_w, big1, nullptr, nullptr, BT, FF, DD, 1.0f);
    sgemm_kernel<EPI_SILUMUL><<<gF, blk>>>(xn, up_w, big2, nullptr, big1, BT, FF, DD, 1.0f);
    sgemm_kernel<EPI_RESID><<<gD, blk>>>(big2, down_w, out, nullptr, out, BT, DD, FF, 1.0f);
}

// round 4
// speedup vs baseline: 1.5055x; 1.5055x over previous
#include <cuda_runtime.h>
#include <cstdint>
#include <mma.h>
#include <math.h>

using namespace nvcuda;

// ---------------------------------------------------------------------------
// Problem constants (fixed shapes from reference setup_inputs)
// ---------------------------------------------------------------------------
#define BB 2
#define TT 4096
#define DD 1024
#define FF 4096
#define SS 4096
#define BT (BB * TT)          // 8192
#define BTD ((size_t)BT * DD) // 8,388,608
#define BTF ((size_t)BT * FF) // 33,554,432
#define NC 64                 // scan chunks
#define CH 64                 // chunk length (NC*CH == TT)
#define BDNC ((size_t)BB * DD * NC) // 131072

// Scratch layout in one big __device__ array (allocated at module load — legal)
__device__ float g_scratch[4 * BTD + 2 * BTF + 3 * BDNC + 4 * (size_t)BT];

#define OFF_XN   ((size_t)0)
#define OFF_CONV (OFF_XN + BTD)          // also reused as q
#define OFF_Z    (OFF_CONV + BTD)        // also reused as retrieved
#define OFF_HT   (OFF_Z + BTD)
#define OFF_BIG1 (OFF_HT + BTD)          // scores / gate preact
#define OFF_BIG2 (OFF_BIG1 + BTF)        // silu(gate)*up
#define OFF_SA   (OFF_BIG2 + BTF)
#define OFF_SB   (OFF_SA + BDNC)
#define OFF_HS   (OFF_SB + BDNC)
#define OFF_TV   (OFF_HS + BDNC)
#define OFF_TI   (OFF_TV + (size_t)BT * 2)

// ---------------------------------------------------------------------------
// RMSNorm: one block per row of D=1024, 256 threads * float4
// ---------------------------------------------------------------------------
__global__ void __launch_bounds__(256) rmsnorm_kernel(
    const float* __restrict__ x, const float* __restrict__ w,
    float* __restrict__ out)
{
    const size_t row = blockIdx.x;
    const int tid = threadIdx.x;
    const float4* xr = (const float4*)(x + row * DD);
    float4 a = xr[tid];
    float ss = a.x * a.x + a.y * a.y + a.z * a.z + a.w * a.w;
    #pragma unroll
    for (int o = 16; o; o >>= 1) ss += __shfl_xor_sync(0xffffffffu, ss, o);
    __shared__ float wss[8];
    if ((tid & 31) == 0) wss[tid >> 5] = ss;
    __syncthreads();
    if (tid < 8) {
        float v = wss[tid];
        #pragma unroll
        for (int o = 4; o; o >>= 1) v += __shfl_xor_sync(0xffu, v, o);
        if (tid == 0) wss[0] = v;
    }
    __syncthreads();
    const float inv = rsqrtf(wss[0] * (1.0f / DD) + 1e-6f);
    float4 wv = ((const float4*)w)[tid];
    float4 o4;
    o4.x = a.x * wv.x * inv;
    o4.y = a.y * wv.y * inv;
    o4.z = a.z * wv.z * inv;
    o4.w = a.w * wv.w * inv;
    ((float4*)(out + row * DD))[tid] = o4;
}

// ---------------------------------------------------------------------------
// Multi-scale causal depthwise conv (k=3,7,15 summed).
// ---------------------------------------------------------------------------
__global__ void __launch_bounds__(256) conv_kernel(
    const float* __restrict__ xn,
    const float* __restrict__ w3, const float* __restrict__ w7,
    const float* __restrict__ w15, float* __restrict__ out)
{
    const size_t idx = (size_t)blockIdx.x * blockDim.x + threadIdx.x;
    const int d = (int)(idx & (DD - 1));
    const size_t bt = idx / DD;
    const int t = (int)(bt & (TT - 1));
    const int b = (int)(bt / TT);
    const float* base = xn + (size_t)b * TT * DD + d;
    float acc = 0.0f;
    #pragma unroll
    for (int j = 0; j < 15; j++) {
        int tt = t - 14 + j;
        if (tt < 0) continue;
        float wsum = w15[d * 15 + j];
        if (j >= 8)  wsum += w7[d * 7 + (j - 8)];
        if (j >= 12) wsum += w3[d * 3 + (j - 12)];
        acc += wsum * base[(size_t)tt * DD];
    }
    out[idx] = acc;
}

// ---------------------------------------------------------------------------
// tf32 tensor-core GEMM: C[M,N] = epi(A[M,K] @ W[N,K]^T)
// 128x128 block tile, K-tile 32, 8 warps (4x2), each warp 32x64 via 2x4
// m16n16k8 wmma fragments. cp.async double-buffered smem, pad 36.
// ---------------------------------------------------------------------------
#define EPI_NONE    0
#define EPI_SCALE   1
#define EPI_BIAS    2
#define EPI_SIGBIAS 3
#define EPI_RESID   4
#define EPI_SILUMUL 5

#define LDT 36                   // smem tile leading dim (conflict-free)
#define TILE_F (128 * LDT)       // floats per tile buffer
#define CLD 132                  // epilogue smem leading dim
#define SMEM_BYTES (4 * TILE_F * 4)   // 73728 B (>= 128*CLD*4 = 67584)

__device__ __forceinline__ void cpasync16(unsigned saddr, const void* gptr) {
    asm volatile("cp.async.cg.shared.global [%0], [%1], 16;\n"
                 :: "r"(saddr), "l"(gptr));
}

template <int EPI>
__global__ void __launch_bounds__(256, 2) tgemm_kernel(
    const float* __restrict__ A, const float* __restrict__ W,
    float* __restrict__ C, const float* __restrict__ bias,
    const float* __restrict__ extra,
    int M, int N, int K, float scale)
{
    extern __shared__ float smem[];
    const int tid  = threadIdx.x;
    const int warp = tid >> 5;
    const int wm   = warp & 3;      // 0..3 -> 32-row slice
    const int wn   = warp >> 2;     // 0..1 -> 64-col slice
    const int bm   = blockIdx.y * 128;
    const int bn   = blockIdx.x * 128;

    float* Abuf[2] = { smem,              smem + TILE_F };
    float* Bbuf[2] = { smem + 2 * TILE_F, smem + 3 * TILE_F };
    const unsigned sA[2] = { (unsigned)__cvta_generic_to_shared(Abuf[0]),
                             (unsigned)__cvta_generic_to_shared(Abuf[1]) };
    const unsigned sB[2] = { (unsigned)__cvta_generic_to_shared(Bbuf[0]),
                             (unsigned)__cvta_generic_to_shared(Bbuf[1]) };

    wmma::fragment<wmma::accumulator, 16, 16, 8, float> acc[2][4];
    #pragma unroll
    for (int i = 0; i < 2; i++)
        #pragma unroll
        for (int j = 0; j < 4; j++)
            wmma::fill_fragment(acc[i][j], 0.0f);

    const int KT = K >> 5;

    auto load_tile = [&](int kt, int b) {
        const float* Ag = A + (size_t)bm * K + (kt << 5);
        const float* Bg = W + (size_t)bn * K + (kt << 5);
        #pragma unroll
        for (int j = 0; j < 4; j++) {
            const int i   = tid + (j << 8);
            const int row = i >> 3;
            const int seg = (i & 7) << 2;
            cpasync16(sA[b] + (unsigned)(row * LDT + seg) * 4,
                      Ag + (size_t)row * K + seg);
            cpasync16(sB[b] + (unsigned)(row * LDT + seg) * 4,
                      Bg + (size_t)row * K + seg);
        }
    };

    load_tile(0, 0);
    asm volatile("cp.async.commit_group;\n");

    int buf = 0;
    for (int kt = 0; kt < KT; kt++) {
        if (kt + 1 < KT) {
            load_tile(kt + 1, buf ^ 1);
            asm volatile("cp.async.commit_group;\n");
            asm volatile("cp.async.wait_group 1;\n");
        } else {
            asm volatile("cp.async.wait_group 0;\n");
        }
        __syncthreads();

        const float* As = Abuf[buf];
        const float* Bs = Bbuf[buf];
        #pragma unroll
        for (int kk = 0; kk < 4; kk++) {
            wmma::fragment<wmma::matrix_a, 16, 16, 8, wmma::precision::tf32,
                           wmma::row_major> af[2];
            wmma::fragment<wmma::matrix_b, 16, 16, 8, wmma::precision::tf32,
                           wmma::col_major> bf[4];
            #pragma unroll
            for (int i = 0; i < 2; i++) {
                wmma::load_matrix_sync(af[i],
                    As + (wm * 32 + i * 16) * LDT + kk * 8, LDT);
                #pragma unroll
                for (int e = 0; e < af[i].num_elements; e++)
                    af[i].x[e] = wmma::__float_to_tf32(af[i].x[e]);
            }
            #pragma unroll
            for (int j = 0; j < 4; j++) {
                wmma::load_matrix_sync(bf[j],
                    Bs + (wn * 64 + j * 16) * LDT + kk * 8, LDT);
                #pragma unroll
                for (int e = 0; e < bf[j].num_elements; e++)
                    bf[j].x[e] = wmma::__float_to_tf32(bf[j].x[e]);
            }
            #pragma unroll
            for (int i = 0; i < 2; i++)
                #pragma unroll
                for (int j = 0; j < 4; j++)
                    wmma::mma_sync(acc[i][j], af[i], bf[j], acc[i][j]);
        }
        buf ^= 1;
        __syncthreads();
    }

    // epilogue via smem for vectorized, fused stores
    float* Cs = smem;   // 128 x CLD
    #pragma unroll
    for (int i = 0; i < 2; i++)
        #pragma unroll
        for (int j = 0; j < 4; j++)
            wmma::store_matrix_sync(
                Cs + (wm * 32 + i * 16) * CLD + wn * 64 + j * 16,
                acc[i][j], CLD, wmma::mem_row_major);
    __syncthreads();

    #pragma unroll
    for (int it = 0; it < 16; it++) {
        const int idx = tid + (it << 8);     // float4 index, 0..4095
        const int r = idx >> 5;
        const int c = (idx & 31) << 2;
        float4 v4 = *(const float4*)(Cs + r * CLD + c);
        const size_t off = (size_t)(bm + r) * N + bn + c;
        float v[4] = { v4.x, v4.y, v4.z, v4.w };
        #pragma unroll
        for (int q = 0; q < 4; q++) {
            if (EPI == EPI_SCALE) {
                v[q] *= scale;
            } else if (EPI == EPI_BIAS) {
                v[q] += bias[bn + c + q];
            } else if (EPI == EPI_SIGBIAS) {
                v[q] += bias[bn + c + q];
                v[q] = 1.0f / (1.0f + expf(-v[q]));
            } else if (EPI == EPI_RESID) {
                v[q] += extra[off + q];
            } else if (EPI == EPI_SILUMUL) {
                const float g = extra[off + q];
                v[q] *= g / (1.0f + expf(-g));
            }
        }
        float4 o4 = { v[0], v[1], v[2], v[3] };
        *(float4*)(C + off) = o4;
    }
}

// ---------------------------------------------------------------------------
// MinGRU chunked scan (3 passes)
// ---------------------------------------------------------------------------
__global__ void __launch_bounds__(256) scan1_kernel(
    const float* __restrict__ z, const float* __restrict__ ht,
    float* __restrict__ Aout, float* __restrict__ Bout)
{
    const int tid = blockIdx.x * blockDim.x + threadIdx.x; // < B*D*NC
    const int d = tid & (DD - 1);
    const int r = tid / DD;
    const int c = r & (NC - 1);
    const int b = r / NC;
    const size_t base = ((size_t)b * TT + (size_t)c * CH) * DD + d;
    float Aa = 1.0f, Bb = 0.0f;
    #pragma unroll 4
    for (int t = 0; t < CH; t++) {
        const float zt = z[base + (size_t)t * DD];
        const float hh = ht[base + (size_t)t * DD];
        const float a = 1.0f - zt;
        Bb = a * Bb + zt * hh;
        Aa *= a;
    }
    Aout[tid] = Aa;
    Bout[tid] = Bb;
}

__global__ void __launch_bounds__(256) scan2_kernel(
    const float* __restrict__ h_prev, const float* __restrict__ Ain,
    const float* __restrict__ Bin, float* __restrict__ hstart,
    float* __restrict__ hlast)
{
    const int tid = blockIdx.x * blockDim.x + threadIdx.x;
    if (tid >= BB * DD) return;
    const int d = tid & (DD - 1);
    const int b = tid / DD;
    float h = h_prev[tid];
    for (int c = 0; c < NC; c++) {
        const size_t i = ((size_t)b * NC + c) * DD + d;
        hstart[i] = h;
        h = Ain[i] * h + Bin[i];
    }
    hlast[tid] = h;
}

__global__ void __launch_bounds__(256) scan3_kernel(
    const float* __restrict__ z, const float* __restrict__ ht,
    const float* __restrict__ hstart, float* __restrict__ xout)
{
    const int tid = blockIdx.x * blockDim.x + threadIdx.x;
    const int d = tid & (DD - 1);
    const int r = tid / DD;
    const int c = r & (NC - 1);
    const int b = r / NC;
    const size_t base = ((size_t)b * TT + (size_t)c * CH) * DD + d;
    float h = hstart[tid];
    for (int t = 0; t < CH; t++) {
        const float zt = z[base + (size_t)t * DD];
        const float hh = ht[base + (size_t)t * DD];
        h = (1.0f - zt) * h + zt * hh;
        xout[base + (size_t)t * DD] += h;
    }
}

// ---------------------------------------------------------------------------
// Top-2 over S=4096 scores per row
// ---------------------------------------------------------------------------
__device__ __forceinline__ void top2_insert(float v, int i,
    float& v1, int& i1, float& v2, int& i2)
{
    if (v > v1 || (v == v1 && i < i1)) { v2 = v1; i2 = i1; v1 = v; i1 = i; }
    else if (v > v2 || (v == v2 && i < i2)) { v2 = v; i2 = i; }
}

__global__ void __launch_bounds__(256) top2_kernel(
    const float* __restrict__ scores, float* __restrict__ topv,
    int* __restrict__ topi)
{
    const int row = blockIdx.x;
    const int tid = threadIdx.x;
    const float* sr = scores + (size_t)row * SS;
    float v1 = -3.4e38f, v2 = -3.4e38f;
    int i1 = 0x7fffffff, i2 = 0x7fffffff;
    for (int s = tid; s < SS; s += 256)
        top2_insert(sr[s], s, v1, i1, v2, i2);
    __shared__ float sv1[256], sv2[256];
    __shared__ int si1[256], si2[256];
    sv1[tid] = v1; sv2[tid] = v2; si1[tid] = i1; si2[tid] = i2;
    __syncthreads();
    for (int o = 128; o; o >>= 1) {
        if (tid < o) {
            float a1 = sv1[tid], a2 = sv2[tid];
            int b1 = si1[tid], b2 = si2[tid];
            top2_insert(sv1[tid + o], si1[tid + o], a1, b1, a2, b2);
            top2_insert(sv2[tid + o], si2[tid + o], a1, b1, a2, b2);
            sv1[tid] = a1; sv2[tid] = a2; si1[tid] = b1; si2[tid] = b2;
        }
        __syncthreads();
    }
    if (tid == 0) {
        topv[row * 2 + 0] = sv1[0];
        topv[row * 2 + 1] = sv2[0];
        topi[row * 2 + 0] = si1[0];
        topi[row * 2 + 1] = si2[0];
    }
}

// retrieved[row, d] = softmax(top2) . slot_values[ids]
__global__ void __launch_bounds__(256) gather_kernel(
    const float* __restrict__ topv, const int* __restrict__ topi,
    const float* __restrict__ V, float* __restrict__ out)
{
    const size_t idx = (size_t)blockIdx.x * blockDim.x + threadIdx.x;
    const int d = (int)(idx & (DD - 1));
    const size_t row = idx / DD;
    const float v1 = topv[row * 2 + 0];
    const float v2 = topv[row * 2 + 1];
    const int i1 = topi[row * 2 + 0];
    const int i2 = topi[row * 2 + 1];
    const float e = expf(v2 - v1);            // v2 <= v1
    const float inv = 1.0f / (1.0f + e);
    const float w1 = inv, w2 = e * inv;
    out[idx] = w1 * V[(size_t)i1 * DD + d] + w2 * V[(size_t)i2 * DD + d];
}

// ---------------------------------------------------------------------------
// Launch sequence
// ---------------------------------------------------------------------------
extern "C" void kernel_launch(void* const* d_in, const int* in_sizes, int n_in,
                              void* d_out, int out_size)
{
    (void)in_sizes; (void)n_in; (void)out_size;
    const float* x        = (const float*)d_in[0];
    const float* h_prev   = (const float*)d_in[1];
    const float* norm1_w  = (const float*)d_in[2];
    const float* conv3_w  = (const float*)d_in[3];
    const float* conv7_w  = (const float*)d_in[4];
    const float* conv15_w = (const float*)d_in[5];
    const float* mix_w    = (const float*)d_in[6];
    const float* norm2_w  = (const float*)d_in[7];
    const float* Wz_w     = (const float*)d_in[8];
    const float* Wz_b     = (const float*)d_in[9];
    const float* Wh_w     = (const float*)d_in[10];
    const float* Wh_b     = (const float*)d_in[11];
    const float* norm3_w  = (const float*)d_in[12];
    const float* slot_k   = (const float*)d_in[13];
    const float* slot_v   = (const float*)d_in[14];
    const float* projq_w  = (const float*)d_in[15];
    const float* projout_w= (const float*)d_in[16];
    const float* norm4_w  = (const float*)d_in[17];
    const float* gate_w   = (const float*)d_in[18];
    const float* up_w     = (const float*)d_in[19];
    const float* down_w   = (const float*)d_in[20];
    float* out = (float*)d_out;

    float* scr = nullptr;
    cudaGetSymbolAddress((void**)&scr, g_scratch);
    float* xn    = scr + OFF_XN;
    float* conv  = scr + OFF_CONV;   // also q
    float* zbuf  = scr + OFF_Z;      // also retrieved
    float* htbuf = scr + OFF_HT;
    float* big1  = scr + OFF_BIG1;   // scores / gate preact
    float* big2  = scr + OFF_BIG2;
    float* scanA = scr + OFF_SA;
    float* scanB = scr + OFF_SB;
    float* hstart= scr + OFF_HS;
    float* topv  = scr + OFF_TV;
    int*   topi  = (int*)(scr + OFF_TI);

    // opt in to 72KB dynamic smem for every instantiation (cheap, idempotent)
    cudaFuncSetAttribute(tgemm_kernel<EPI_NONE>,    cudaFuncAttributeMaxDynamicSharedMemorySize, SMEM_BYTES);
    cudaFuncSetAttribute(tgemm_kernel<EPI_SCALE>,   cudaFuncAttributeMaxDynamicSharedMemorySize, SMEM_BYTES);
    cudaFuncSetAttribute(tgemm_kernel<EPI_BIAS>,    cudaFuncAttributeMaxDynamicSharedMemorySize, SMEM_BYTES);
    cudaFuncSetAttribute(tgemm_kernel<EPI_SIGBIAS>, cudaFuncAttributeMaxDynamicSharedMemorySize, SMEM_BYTES);
    cudaFuncSetAttribute(tgemm_kernel<EPI_RESID>,   cudaFuncAttributeMaxDynamicSharedMemorySize, SMEM_BYTES);
    cudaFuncSetAttribute(tgemm_kernel<EPI_SILUMUL>, cudaFuncAttributeMaxDynamicSharedMemorySize, SMEM_BYTES);

    const dim3 blk(256);
    const dim3 gD(DD / 128, BT / 128);   // N=1024 GEMMs
    const dim3 gF(FF / 128, BT / 128);   // N=4096 GEMMs
    const dim3 gS(SS / 128, BT / 128);   // scores GEMM

    // running x lives in d_out
    cudaMemcpyAsync(out, x, BTD * sizeof(float), cudaMemcpyDeviceToDevice);

    // 1. conv block
    rmsnorm_kernel<<<BT, blk>>>(out, norm1_w, xn);
    conv_kernel<<<(unsigned)(BTD / 256), blk>>>(xn, conv3_w, conv7_w, conv15_w, conv);
    tgemm_kernel<EPI_RESID><<<gD, blk, SMEM_BYTES>>>(conv, mix_w, out, nullptr, out, BT, DD, DD, 1.0f);

    // 2. MinGRU
    rmsnorm_kernel<<<BT, blk>>>(out, norm2_w, xn);
    tgemm_kernel<EPI_SIGBIAS><<<gD, blk, SMEM_BYTES>>>(xn, Wz_w, zbuf, Wz_b, nullptr, BT, DD, DD, 1.0f);
    tgemm_kernel<EPI_BIAS><<<gD, blk, SMEM_BYTES>>>(xn, Wh_w, htbuf, Wh_b, nullptr, BT, DD, DD, 1.0f);
    scan1_kernel<<<(unsigned)(BDNC / 256), blk>>>(zbuf, htbuf, scanA, scanB);
    scan2_kernel<<<(BB * DD + 255) / 256, blk>>>(h_prev, scanA, scanB, hstart, out + BTD);
    scan3_kernel<<<(unsigned)(BDNC / 256), blk>>>(zbuf, htbuf, hstart, out);

    // 3. slot memory, top-2 routing
    rmsnorm_kernel<<<BT, blk>>>(out, norm3_w, xn);
    tgemm_kernel<EPI_NONE><<<gD, blk, SMEM_BYTES>>>(xn, projq_w, conv, nullptr, nullptr, BT, DD, DD, 1.0f);
    tgemm_kernel<EPI_SCALE><<<gS, blk, SMEM_BYTES>>>(conv, slot_k, big1, nullptr, nullptr, BT, SS, DD, 0.03125f);
    top2_kernel<<<BT, blk>>>(big1, topv, topi);
    gather_kernel<<<(unsigned)(BTD / 256), blk>>>(topv, topi, slot_v, zbuf);
    tgemm_kernel<EPI_RESID><<<gD, blk, SMEM_BYTES>>>(zbuf, projout_w, out, nullptr, out, BT, DD, DD, 1.0f);

    // 4. SwiGLU FFN
    rmsnorm_kernel<<<BT, blk>>>(out, norm4_w, xn);
    tgemm_kernel<EPI_NONE><<<gF, blk, SMEM_BYTES>>>(xn, gate_w, big1, nullptr, nullptr, BT, FF, DD, 1.0f);
    tgemm_kernel<EPI_SILUMUL><<<gF, blk, SMEM_BYTES>>>(xn, up_w, big2, nullptr, big1, BT, FF, DD, 1.0f);
    tgemm_kernel<EPI_RESID><<<gD, blk, SMEM_BYTES>>>(big2, down_w, out, nullptr, out, BT, DD, FF, 1.0f);
}

// round 5
// speedup vs baseline: 4.8639x; 3.2308x over previous
#include <cuda_runtime.h>
#include <cuda_fp16.h>
#include <cstdint>
#include <mma.h>
#include <math.h>

using namespace nvcuda;

// ---------------------------------------------------------------------------
// Problem constants
// ---------------------------------------------------------------------------
#define BB 2
#define TT 4096
#define DD 1024
#define FF 4096
#define SS 4096
#define BT (BB * TT)          // 8192
#define BTD ((size_t)BT * DD) // 8,388,608
#define BTF ((size_t)BT * FF) // 33,554,432
#define NC 64
#define CH 64
#define BDNC ((size_t)BB * DD * NC) // 131072

#define MM ((size_t)1048576)          // 1024*1024
#define FMsz (4 * MM)

// fp32 scratch
__device__ float g_scratch[4 * BTD + 2 * BDNC + BDNC + (size_t)BT * 4 + BTF];

#define OFF_XN   ((size_t)0)          // unused fp32 xn (norm1 only)
#define OFF_Z    (OFF_XN + BTD)
#define OFF_HT   (OFF_Z + BTD)
#define OFF_X1   (OFF_HT + BTD)       // spare
#define OFF_SA   (OFF_X1 + BTD)
#define OFF_SB   (OFF_SA + BDNC)
#define OFF_HS   (OFF_SB + BDNC)
#define OFF_TV   (OFF_HS + BDNC)
#define OFF_TI   (OFF_TV + (size_t)BT * 2)
#define OFF_BIG1 (OFF_TI + (size_t)BT * 2)  // scores / gate preact (BTF)

// fp16 pool: 9 weights + 2 BTD activation buffers + 1 BTF buffer
// weights: mix 0, Wz 1M, Wh 2M, projq 3M, projout 4M, slotk 5M(4M),
//          gate 9M, up 13M, down 17M  -> end 21M
#define HOFF_MIX   ((size_t)0)
#define HOFF_WZ    (1 * MM)
#define HOFF_WH    (2 * MM)
#define HOFF_PQ    (3 * MM)
#define HOFF_PO    (4 * MM)
#define HOFF_SK    (5 * MM)
#define HOFF_GATE  (9 * MM)
#define HOFF_UP    (13 * MM)
#define HOFF_DOWN  (17 * MM)
#define HOFF_CONVH (21 * MM)          // BTD, also q / xn4
#define HOFF_XNH   (HOFF_CONVH + BTD) // BTD, xn2/xn3 / retrieved
#define HOFF_BIG2H (HOFF_XNH + BTD)   // BTF
__device__ __half g_half[HOFF_BIG2H + BTF];

// ---------------------------------------------------------------------------
// fp32 -> fp16 cast (vectorized, n % 1024 == 0)
// ---------------------------------------------------------------------------
__global__ void __launch_bounds__(256) cast_kernel(
    const float* __restrict__ src, __half* __restrict__ dst, size_t n)
{
    const size_t i = ((size_t)blockIdx.x * blockDim.x + threadIdx.x) * 4;
    if (i >= n) return;
    float4 v = *(const float4*)(src + i);
    __half2 lo = __floats2half2_rn(v.x, v.y);
    __half2 hi = __floats2half2_rn(v.z, v.w);
    uint2 o = { *(unsigned*)&lo, *(unsigned*)&hi };
    *(uint2*)(dst + i) = o;
}

// ---------------------------------------------------------------------------
// RMSNorm (fp32 out) and RMSNorm (fp16 out)
// ---------------------------------------------------------------------------
template <int HALF_OUT>
__global__ void __launch_bounds__(256) rmsnorm_kernel(
    const float* __restrict__ x, const float* __restrict__ w,
    float* __restrict__ out, __half* __restrict__ outh)
{
    const size_t row = blockIdx.x;
    const int tid = threadIdx.x;
    const float4* xr = (const float4*)(x + row * DD);
    float4 a = xr[tid];
    float ss = a.x * a.x + a.y * a.y + a.z * a.z + a.w * a.w;
    #pragma unroll
    for (int o = 16; o; o >>= 1) ss += __shfl_xor_sync(0xffffffffu, ss, o);
    __shared__ float wss[8];
    if ((tid & 31) == 0) wss[tid >> 5] = ss;
    __syncthreads();
    if (tid < 8) {
        float v = wss[tid];
        #pragma unroll
        for (int o = 4; o; o >>= 1) v += __shfl_xor_sync(0xffu, v, o);
        if (tid == 0) wss[0] = v;
    }
    __syncthreads();
    const float inv = rsqrtf(wss[0] * (1.0f / DD) + 1e-6f);
    float4 wv = ((const float4*)w)[tid];
    float4 o4;
    o4.x = a.x * wv.x * inv;
    o4.y = a.y * wv.y * inv;
    o4.z = a.z * wv.z * inv;
    o4.w = a.w * wv.w * inv;
    if (HALF_OUT) {
        __half2 lo = __floats2half2_rn(o4.x, o4.y);
        __half2 hi = __floats2half2_rn(o4.z, o4.w);
        uint2 u = { *(unsigned*)&lo, *(unsigned*)&hi };
        *(uint2*)(outh + row * DD + tid * 4) = u;
    } else {
        ((float4*)(out + row * DD))[tid] = o4;
    }
}

// ---------------------------------------------------------------------------
// Multi-scale causal depthwise conv -> fp16 out
// ---------------------------------------------------------------------------
__global__ void __launch_bounds__(256) conv_kernel(
    const float* __restrict__ xn,
    const float* __restrict__ w3, const float* __restrict__ w7,
    const float* __restrict__ w15, __half* __restrict__ out)
{
    const size_t idx = (size_t)blockIdx.x * blockDim.x + threadIdx.x;
    const int d = (int)(idx & (DD - 1));
    const size_t bt = idx / DD;
    const int t = (int)(bt & (TT - 1));
    const int b = (int)(bt / TT);
    const float* base = xn + (size_t)b * TT * DD + d;
    float acc = 0.0f;
    #pragma unroll
    for (int j = 0; j < 15; j++) {
        int tt = t - 14 + j;
        if (tt < 0) continue;
        float wsum = w15[d * 15 + j];
        if (j >= 8)  wsum += w7[d * 7 + (j - 8)];
        if (j >= 12) wsum += w3[d * 3 + (j - 12)];
        acc += wsum * base[(size_t)tt * DD];
    }
    out[idx] = __float2half_rn(acc);
}

// ---------------------------------------------------------------------------
// fp16 tensor-core GEMM: C[M,N] = epi(A[M,K] @ W[N,K]^T), A/W fp16, acc fp32.
// 128x128 tile, K-tile 64, double-buffered cp.async, 8 warps 32x64 each,
// wmma m16n16k16.
// ---------------------------------------------------------------------------
#define EPI_NONE    0
#define EPI_SCALE   1
#define EPI_BIAS    2
#define EPI_SIGBIAS 3
#define EPI_RESID   4
#define EPI_SILUMUL 5

#define KTILE 64
#define LDTH 72                    // halves per row (64 + 8 pad) -> 144B stride
#define TILEH (128 * LDTH)         // halves per tile buffer
#define CLD 132
#define SMEM_BYTES (4 * TILEH * 2 > 128 * CLD * 4 ? 4 * TILEH * 2 : 128 * CLD * 4)

__device__ __forceinline__ void cpasync16(unsigned saddr, const void* gptr) {
    asm volatile("cp.async.cg.shared.global [%0], [%1], 16;\n"
                 :: "r"(saddr), "l"(gptr));
}

template <int EPI, int HOUT>
__global__ void __launch_bounds__(256, 2) tgemm_kernel(
    const __half* __restrict__ A, const __half* __restrict__ W,
    void* __restrict__ Cout, const float* __restrict__ bias,
    const float* __restrict__ extra,
    int M, int N, int K, float scale)
{
    extern __shared__ __align__(16) char smem_raw[];
    __half* smem = (__half*)smem_raw;
    const int tid  = threadIdx.x;
    const int warp = tid >> 5;
    const int wm   = warp & 3;
    const int wn   = warp >> 2;
    const int bm   = blockIdx.y * 128;
    const int bn   = blockIdx.x * 128;

    __half* Abuf[2] = { smem,             smem + TILEH };
    __half* Bbuf[2] = { smem + 2 * TILEH, smem + 3 * TILEH };
    const unsigned sA[2] = { (unsigned)__cvta_generic_to_shared(Abuf[0]),
                             (unsigned)__cvta_generic_to_shared(Abuf[1]) };
    const unsigned sB[2] = { (unsigned)__cvta_generic_to_shared(Bbuf[0]),
                             (unsigned)__cvta_generic_to_shared(Bbuf[1]) };

    wmma::fragment<wmma::accumulator, 16, 16, 16, float> acc[2][4];
    #pragma unroll
    for (int i = 0; i < 2; i++)
        #pragma unroll
        for (int j = 0; j < 4; j++)
            wmma::fill_fragment(acc[i][j], 0.0f);

    const int KT = K / KTILE;

    // per K-tile: 128 rows x 64 halves = 1024 chunks of 8 halves (16B)
    auto load_tile = [&](int kt, int b) {
        const __half* Ag = A + (size_t)bm * K + kt * KTILE;
        const __half* Bg = W + (size_t)bn * K + kt * KTILE;
        #pragma unroll
        for (int j = 0; j < 4; j++) {
            const int i   = tid + (j << 8);
            const int row = i >> 3;
            const int seg = (i & 7) << 3;
            cpasync16(sA[b] + (unsigned)(row * LDTH + seg) * 2,
                      Ag + (size_t)row * K + seg);
            cpasync16(sB[b] + (unsigned)(row * LDTH + seg) * 2,
                      Bg + (size_t)row * K + seg);
        }
    };

    load_tile(0, 0);
    asm volatile("cp.async.commit_group;\n");

    int buf = 0;
    for (int kt = 0; kt < KT; kt++) {
        if (kt + 1 < KT) {
            load_tile(kt + 1, buf ^ 1);
            asm volatile("cp.async.commit_group;\n");
            asm volatile("cp.async.wait_group 1;\n");
        } else {
            asm volatile("cp.async.wait_group 0;\n");
        }
        __syncthreads();

        const __half* As = Abuf[buf];
        const __half* Bs = Bbuf[buf];
        #pragma unroll
        for (int kk = 0; kk < 4; kk++) {
            wmma::fragment<wmma::matrix_a, 16, 16, 16, __half, wmma::row_major> af[2];
            wmma::fragment<wmma::matrix_b, 16, 16, 16, __half, wmma::col_major> bf[4];
            #pragma unroll
            for (int i = 0; i < 2; i++)
                wmma::load_matrix_sync(af[i],
                    As + (wm * 32 + i * 16) * LDTH + kk * 16, LDTH);
            #pragma unroll
            for (int j = 0; j < 4; j++)
                wmma::load_matrix_sync(bf[j],
                    Bs + (wn * 64 + j * 16) * LDTH + kk * 16, LDTH);
            #pragma unroll
            for (int i = 0; i < 2; i++)
                #pragma unroll
                for (int j = 0; j < 4; j++)
                    wmma::mma_sync(acc[i][j], af[i], bf[j], acc[i][j]);
        }
        buf ^= 1;
        __syncthreads();
    }

    // epilogue via smem
    float* Cs = (float*)smem_raw;   // 128 x CLD
    #pragma unroll
    for (int i = 0; i < 2; i++)
        #pragma unroll
        for (int j = 0; j < 4; j++)
            wmma::store_matrix_sync(
                Cs + (wm * 32 + i * 16) * CLD + wn * 64 + j * 16,
                acc[i][j], CLD, wmma::mem_row_major);
    __syncthreads();

    #pragma unroll
    for (int it = 0; it < 16; it++) {
        const int idx = tid + (it << 8);
        const int r = idx >> 5;
        const int c = (idx & 31) << 2;
        float4 v4 = *(const float4*)(Cs + r * CLD + c);
        const size_t off = (size_t)(bm + r) * N + bn + c;
        float v[4] = { v4.x, v4.y, v4.z, v4.w };
        #pragma unroll
        for (int q = 0; q < 4; q++) {
            if (EPI == EPI_SCALE) {
                v[q] *= scale;
            } else if (EPI == EPI_BIAS) {
                v[q] += bias[bn + c + q];
            } else if (EPI == EPI_SIGBIAS) {
                v[q] += bias[bn + c + q];
                v[q] = 1.0f / (1.0f + expf(-v[q]));
            } else if (EPI == EPI_RESID) {
                v[q] += extra[off + q];
            } else if (EPI == EPI_SILUMUL) {
                const float g = extra[off + q];
                v[q] *= g / (1.0f + expf(-g));
            }
        }
        if (HOUT) {
            __half2 lo = __floats2half2_rn(v[0], v[1]);
            __half2 hi = __floats2half2_rn(v[2], v[3]);
            uint2 u = { *(unsigned*)&lo, *(unsigned*)&hi };
            *(uint2*)((__half*)Cout + off) = u;
        } else {
            float4 o4 = { v[0], v[1], v[2], v[3] };
            *(float4*)((float*)Cout + off) = o4;
        }
    }
}

// ---------------------------------------------------------------------------
// MinGRU chunked scan (3 passes)
// ---------------------------------------------------------------------------
__global__ void __launch_bounds__(256) scan1_kernel(
    const float* __restrict__ z, const float* __restrict__ ht,
    float* __restrict__ Aout, float* __restrict__ Bout)
{
    const int tid = blockIdx.x * blockDim.x + threadIdx.x;
    const int d = tid & (DD - 1);
    const int r = tid / DD;
    const int c = r & (NC - 1);
    const int b = r / NC;
    const size_t base = ((size_t)b * TT + (size_t)c * CH) * DD + d;
    float Aa = 1.0f, Bb = 0.0f;
    #pragma unroll 4
    for (int t = 0; t < CH; t++) {
        const float zt = z[base + (size_t)t * DD];
        const float hh = ht[base + (size_t)t * DD];
        const float a = 1.0f - zt;
        Bb = a * Bb + zt * hh;
        Aa *= a;
    }
    Aout[tid] = Aa;
    Bout[tid] = Bb;
}

__global__ void __launch_bounds__(256) scan2_kernel(
    const float* __restrict__ h_prev, const float* __restrict__ Ain,
    const float* __restrict__ Bin, float* __restrict__ hstart,
    float* __restrict__ hlast)
{
    const int tid = blockIdx.x * blockDim.x + threadIdx.x;
    if (tid >= BB * DD) return;
    const int d = tid & (DD - 1);
    const int b = tid / DD;
    float h = h_prev[tid];
    for (int c = 0; c < NC; c++) {
        const size_t i = ((size_t)b * NC + c) * DD + d;
        hstart[i] = h;
        h = Ain[i] * h + Bin[i];
    }
    hlast[tid] = h;
}

__global__ void __launch_bounds__(256) scan3_kernel(
    const float* __restrict__ z, const float* __restrict__ ht,
    const float* __restrict__ hstart, float* __restrict__ xout)
{
    const int tid = blockIdx.x * blockDim.x + threadIdx.x;
    const int d = tid & (DD - 1);
    const int r = tid / DD;
    const int c = r & (NC - 1);
    const int b = r / NC;
    const size_t base = ((size_t)b * TT + (size_t)c * CH) * DD + d;
    float h = hstart[tid];
    for (int t = 0; t < CH; t++) {
        const float zt = z[base + (size_t)t * DD];
        const float hh = ht[base + (size_t)t * DD];
        h = (1.0f - zt) * h + zt * hh;
        xout[base + (size_t)t * DD] += h;
    }
}

// ---------------------------------------------------------------------------
// Top-2 over S=4096 scores per row
// ---------------------------------------------------------------------------
__device__ __forceinline__ void top2_insert(float v, int i,
    float& v1, int& i1, float& v2, int& i2)
{
    if (v > v1 || (v == v1 && i < i1)) { v2 = v1; i2 = i1; v1 = v; i1 = i; }
    else if (v > v2 || (v == v2 && i < i2)) { v2 = v; i2 = i; }
}

__global__ void __launch_bounds__(256) top2_kernel(
    const float* __restrict__ scores, float* __restrict__ topv,
    int* __restrict__ topi)
{
    const int row = blockIdx.x;
    const int tid = threadIdx.x;
    const float* sr = scores + (size_t)row * SS;
    float v1 = -3.4e38f, v2 = -3.4e38f;
    int i1 = 0x7fffffff, i2 = 0x7fffffff;
    for (int s = tid; s < SS; s += 256)
        top2_insert(sr[s], s, v1, i1, v2, i2);
    __shared__ float sv1[256], sv2[256];
    __shared__ int si1[256], si2[256];
    sv1[tid] = v1; sv2[tid] = v2; si1[tid] = i1; si2[tid] = i2;
    __syncthreads();
    for (int o = 128; o; o >>= 1) {
        if (tid < o) {
            float a1 = sv1[tid], a2 = sv2[tid];
            int b1 = si1[tid], b2 = si2[tid];
            top2_insert(sv1[tid + o], si1[tid + o], a1, b1, a2, b2);
            top2_insert(sv2[tid + o], si2[tid + o], a1, b1, a2, b2);
            sv1[tid] = a1; sv2[tid] = a2; si1[tid] = b1; si2[tid] = b2;
        }
        __syncthreads();
    }
    if (tid == 0) {
        topv[row * 2 + 0] = sv1[0];
        topv[row * 2 + 1] = sv2[0];
        topi[row * 2 + 0] = si1[0];
        topi[row * 2 + 1] = si2[0];
    }
}

// retrieved[row, d] = softmax(top2) . slot_values[ids]  -> fp16 out
__global__ void __launch_bounds__(256) gather_kernel(
    const float* __restrict__ topv, const int* __restrict__ topi,
    const float* __restrict__ V, __half* __restrict__ out)
{
    const size_t idx = (size_t)blockIdx.x * blockDim.x + threadIdx.x;
    const int d = (int)(idx & (DD - 1));
    const size_t row = idx / DD;
    const float v1 = topv[row * 2 + 0];
    const float v2 = topv[row * 2 + 1];
    const int i1 = topi[row * 2 + 0];
    const int i2 = topi[row * 2 + 1];
    const float e = expf(v2 - v1);
    const float inv = 1.0f / (1.0f + e);
    const float w1 = inv, w2 = e * inv;
    out[idx] = __float2half_rn(
        w1 * V[(size_t)i1 * DD + d] + w2 * V[(size_t)i2 * DD + d]);
}

// ---------------------------------------------------------------------------
// Launch sequence
// ---------------------------------------------------------------------------
extern "C" void kernel_launch(void* const* d_in, const int* in_sizes, int n_in,
                              void* d_out, int out_size)
{
    (void)in_sizes; (void)n_in; (void)out_size;
    const float* x        = (const float*)d_in[0];
    const float* h_prev   = (const float*)d_in[1];
    const float* norm1_w  = (const float*)d_in[2];
    const float* conv3_w  = (const float*)d_in[3];
    const float* conv7_w  = (const float*)d_in[4];
    const float* conv15_w = (const float*)d_in[5];
    const float* mix_w    = (const float*)d_in[6];
    const float* norm2_w  = (const float*)d_in[7];
    const float* Wz_w     = (const float*)d_in[8];
    const float* Wz_b     = (const float*)d_in[9];
    const float* Wh_w     = (const float*)d_in[10];
    const float* Wh_b     = (const float*)d_in[11];
    const float* norm3_w  = (const float*)d_in[12];
    const float* slot_k   = (const float*)d_in[13];
    const float* slot_v   = (const float*)d_in[14];
    const float* projq_w  = (const float*)d_in[15];
    const float* projout_w= (const float*)d_in[16];
    const float* norm4_w  = (const float*)d_in[17];
    const float* gate_w   = (const float*)d_in[18];
    const float* up_w     = (const float*)d_in[19];
    const float* down_w   = (const float*)d_in[20];
    float* out = (float*)d_out;

    float* scr = nullptr;
    cudaGetSymbolAddress((void**)&scr, g_scratch);
    __half* hp = nullptr;
    cudaGetSymbolAddress((void**)&hp, g_half);

    float* xn    = scr + OFF_XN;
    float* zbuf  = scr + OFF_Z;
    float* htbuf = scr + OFF_HT;
    float* big1  = scr + OFF_BIG1;
    float* scanA = scr + OFF_SA;
    float* scanB = scr + OFF_SB;
    float* hstart= scr + OFF_HS;
    float* topv  = scr + OFF_TV;
    int*   topi  = (int*)(scr + OFF_TI);

    __half* mixh  = hp + HOFF_MIX;
    __half* Wzh   = hp + HOFF_WZ;
    __half* Whh   = hp + HOFF_WH;
    __half* pqh   = hp + HOFF_PQ;
    __half* poh   = hp + HOFF_PO;
    __half* skh   = hp + HOFF_SK;
    __half* gateh = hp + HOFF_GATE;
    __half* uph   = hp + HOFF_UP;
    __half* downh = hp + HOFF_DOWN;
    __half* convh = hp + HOFF_CONVH;  // conv / q / xn4
    __half* xnh   = hp + HOFF_XNH;    // xn2/xn3 / retrieved
    __half* big2h = hp + HOFF_BIG2H;

    cudaFuncSetAttribute(tgemm_kernel<EPI_RESID,0>,   cudaFuncAttributeMaxDynamicSharedMemorySize, SMEM_BYTES);
    cudaFuncSetAttribute(tgemm_kernel<EPI_SIGBIAS,0>, cudaFuncAttributeMaxDynamicSharedMemorySize, SMEM_BYTES);
    cudaFuncSetAttribute(tgemm_kernel<EPI_BIAS,0>,    cudaFuncAttributeMaxDynamicSharedMemorySize, SMEM_BYTES);
    cudaFuncSetAttribute(tgemm_kernel<EPI_NONE,1>,    cudaFuncAttributeMaxDynamicSharedMemorySize, SMEM_BYTES);
    cudaFuncSetAttribute(tgemm_kernel<EPI_NONE,0>,    cudaFuncAttributeMaxDynamicSharedMemorySize, SMEM_BYTES);
    cudaFuncSetAttribute(tgemm_kernel<EPI_SCALE,0>,   cudaFuncAttributeMaxDynamicSharedMemorySize, SMEM_BYTES);
    cudaFuncSetAttribute(tgemm_kernel<EPI_SILUMUL,1>, cudaFuncAttributeMaxDynamicSharedMemorySize, SMEM_BYTES);

    const dim3 blk(256);
    const dim3 gD(DD / 128, BT / 128);
    const dim3 gF(FF / 128, BT / 128);
    const dim3 gS(SS / 128, BT / 128);

    // cast weights to fp16
    cast_kernel<<<(unsigned)(MM / 1024), blk>>>(mix_w,    mixh,  MM);
    cast_kernel<<<(unsigned)(MM / 1024), blk>>>(Wz_w,     Wzh,   MM);
    cast_kernel<<<(unsigned)(MM / 1024), blk>>>(Wh_w,     Whh,   MM);
    cast_kernel<<<(unsigned)(MM / 1024), blk>>>(projq_w,  pqh,   MM);
    cast_kernel<<<(unsigned)(MM / 1024), blk>>>(projout_w,poh,   MM);
    cast_kernel<<<(unsigned)(FMsz / 1024), blk>>>(slot_k, skh,   FMsz);
    cast_kernel<<<(unsigned)(FMsz / 1024), blk>>>(gate_w, gateh, FMsz);
    cast_kernel<<<(unsigned)(FMsz / 1024), blk>>>(up_w,   uph,   FMsz);
    cast_kernel<<<(unsigned)(FMsz / 1024), blk>>>(down_w, downh, FMsz);

    // running x lives in d_out
    cudaMemcpyAsync(out, x, BTD * sizeof(float), cudaMemcpyDeviceToDevice);

    // 1. conv block
    rmsnorm_kernel<0><<<BT, blk>>>(out, norm1_w, xn, nullptr);
    conv_kernel<<<(unsigned)(BTD / 256), blk>>>(xn, conv3_w, conv7_w, conv15_w, convh);
    tgemm_kernel<EPI_RESID,0><<<gD, blk, SMEM_BYTES>>>(convh, mixh, out, nullptr, out, BT, DD, DD, 1.0f);

    // 2. MinGRU
    rmsnorm_kernel<1><<<BT, blk>>>(out, norm2_w, nullptr, xnh);
    tgemm_kernel<EPI_SIGBIAS,0><<<gD, blk, SMEM_BYTES>>>(xnh, Wzh, zbuf, Wz_b, nullptr, BT, DD, DD, 1.0f);
    tgemm_kernel<EPI_BIAS,0><<<gD, blk, SMEM_BYTES>>>(xnh, Whh, htbuf, Wh_b, nullptr, BT, DD, DD, 1.0f);
    scan1_kernel<<<(unsigned)(BDNC / 256), blk>>>(zbuf, htbuf, scanA, scanB);
    scan2_kernel<<<(BB * DD + 255) / 256, blk>>>(h_prev, scanA, scanB, hstart, out + BTD);
    scan3_kernel<<<(unsigned)(BDNC / 256), blk>>>(zbuf, htbuf, hstart, out);

    // 3. slot memory
    rmsnorm_kernel<1><<<BT, blk>>>(out, norm3_w, nullptr, xnh);
    tgemm_kernel<EPI_NONE,1><<<gD, blk, SMEM_BYTES>>>(xnh, pqh, convh, nullptr, nullptr, BT, DD, DD, 1.0f);
    tgemm_kernel<EPI_SCALE,0><<<gS, blk, SMEM_BYTES>>>(convh, skh, big1, nullptr, nullptr, BT, SS, DD, 0.03125f);
    top2_kernel<<<BT, blk>>>(big1, topv, topi);
    gather_kernel<<<(unsigned)(BTD / 256), blk>>>(topv, topi, slot_v, xnh);
    tgemm_kernel<EPI_RESID,0><<<gD, blk, SMEM_BYTES>>>(xnh, poh, out, nullptr, out, BT, DD, DD, 1.0f);

    // 4. SwiGLU FFN
    rmsnorm_kernel<1><<<BT, blk>>>(out, norm4_w, nullptr, convh);
    tgemm_kernel<EPI_NONE,0><<<gF, blk, SMEM_BYTES>>>(convh, gateh, big1, nullptr, nullptr, BT, FF, DD, 1.0f);
    tgemm_kernel<EPI_SILUMUL,1><<<gF, blk, SMEM_BYTES>>>(convh, uph, big2h, nullptr, big1, BT, FF, DD, 1.0f);
    tgemm_kernel<EPI_RESID,0><<<gD, blk, SMEM_BYTES>>>(big2h, downh, out, nullptr, out, BT, DD, FF, 1.0f);
}

// round 7
// speedup vs baseline: 5.3337x; 1.0966x over previous
#include <cuda_runtime.h>
#include <cuda_fp16.h>
#include <cstdint>
#include <math.h>

// ---------------------------------------------------------------------------
// Problem constants
// ---------------------------------------------------------------------------
#define BB 2
#define TT 4096
#define DD 1024
#define FF 4096
#define SS 4096
#define BT (BB * TT)          // 8192
#define BTD ((size_t)BT * DD) // 8,388,608
#define BTF ((size_t)BT * FF) // 33,554,432
#define NC 64
#define CH 64
#define BDNC ((size_t)BB * DD * NC) // 131072

#define MM ((size_t)1048576)
#define FMsz (4 * MM)

// fp32 scratch
__device__ float g_scratch[4 * BTD + 2 * BDNC + BDNC + (size_t)BT * 4 + BTF];

#define OFF_XN   ((size_t)0)
#define OFF_Z    (OFF_XN + BTD)
#define OFF_HT   (OFF_Z + BTD)
#define OFF_X1   (OFF_HT + BTD)
#define OFF_SA   (OFF_X1 + BTD)
#define OFF_SB   (OFF_SA + BDNC)
#define OFF_HS   (OFF_SB + BDNC)
#define OFF_TV   (OFF_HS + BDNC)
#define OFF_TI   (OFF_TV + (size_t)BT * 2)
#define OFF_BIG1 (OFF_TI + (size_t)BT * 2)  // scores / gate preact (BTF)

// fp16 pool
#define HOFF_MIX   ((size_t)0)
#define HOFF_WZ    (1 * MM)
#define HOFF_WH    (2 * MM)
#define HOFF_PQ    (3 * MM)
#define HOFF_PO    (4 * MM)
#define HOFF_SK    (5 * MM)
#define HOFF_GATE  (9 * MM)
#define HOFF_UP    (13 * MM)
#define HOFF_DOWN  (17 * MM)
#define HOFF_CONVH (21 * MM)
#define HOFF_XNH   (HOFF_CONVH + BTD)
#define HOFF_BIG2H (HOFF_XNH + BTD)
__device__ __half g_half[HOFF_BIG2H + BTF];

// ---------------------------------------------------------------------------
// fp32 -> fp16 cast
// ---------------------------------------------------------------------------
__global__ void __launch_bounds__(256) cast_kernel(
    const float* __restrict__ src, __half* __restrict__ dst, size_t n)
{
    const size_t i = ((size_t)blockIdx.x * blockDim.x + threadIdx.x) * 4;
    if (i >= n) return;
    float4 v = *(const float4*)(src + i);
    __half2 lo = __floats2half2_rn(v.x, v.y);
    __half2 hi = __floats2half2_rn(v.z, v.w);
    uint2 o = { *(unsigned*)&lo, *(unsigned*)&hi };
    *(uint2*)(dst + i) = o;
}

// ---------------------------------------------------------------------------
// RMSNorm (fp32 or fp16 out)
// ---------------------------------------------------------------------------
template <int HALF_OUT>
__global__ void __launch_bounds__(256) rmsnorm_kernel(
    const float* __restrict__ x, const float* __restrict__ w,
    float* __restrict__ out, __half* __restrict__ outh)
{
    const size_t row = blockIdx.x;
    const int tid = threadIdx.x;
    const float4* xr = (const float4*)(x + row * DD);
    float4 a = xr[tid];
    float ss = a.x * a.x + a.y * a.y + a.z * a.z + a.w * a.w;
    #pragma unroll
    for (int o = 16; o; o >>= 1) ss += __shfl_xor_sync(0xffffffffu, ss, o);
    __shared__ float wss[8];
    if ((tid & 31) == 0) wss[tid >> 5] = ss;
    __syncthreads();
    if (tid < 8) {
        float v = wss[tid];
        #pragma unroll
        for (int o = 4; o; o >>= 1) v += __shfl_xor_sync(0xffu, v, o);
        if (tid == 0) wss[0] = v;
    }
    __syncthreads();
    const float inv = rsqrtf(wss[0] * (1.0f / DD) + 1e-6f);
    float4 wv = ((const float4*)w)[tid];
    float4 o4;
    o4.x = a.x * wv.x * inv;
    o4.y = a.y * wv.y * inv;
    o4.z = a.z * wv.z * inv;
    o4.w = a.w * wv.w * inv;
    if (HALF_OUT) {
        __half2 lo = __floats2half2_rn(o4.x, o4.y);
        __half2 hi = __floats2half2_rn(o4.z, o4.w);
        uint2 u = { *(unsigned*)&lo, *(unsigned*)&hi };
        *(uint2*)(outh + row * DD + tid * 4) = u;
    } else {
        ((float4*)(out + row * DD))[tid] = o4;
    }
}

// ---------------------------------------------------------------------------
// Multi-scale causal depthwise conv -> fp16 out
// ---------------------------------------------------------------------------
__global__ void __launch_bounds__(256) conv_kernel(
    const float* __restrict__ xn,
    const float* __restrict__ w3, const float* __restrict__ w7,
    const float* __restrict__ w15, __half* __restrict__ out)
{
    const size_t idx = (size_t)blockIdx.x * blockDim.x + threadIdx.x;
    const int d = (int)(idx & (DD - 1));
    const size_t bt = idx / DD;
    const int t = (int)(bt & (TT - 1));
    const int b = (int)(bt / TT);
    const float* base = xn + (size_t)b * TT * DD + d;
    float acc = 0.0f;
    #pragma unroll
    for (int j = 0; j < 15; j++) {
        int tt = t - 14 + j;
        if (tt < 0) continue;
        float wsum = w15[d * 15 + j];
        if (j >= 8)  wsum += w7[d * 7 + (j - 8)];
        if (j >= 12) wsum += w3[d * 3 + (j - 12)];
        acc += wsum * base[(size_t)tt * DD];
    }
    out[idx] = __float2half_rn(acc);
}

// ---------------------------------------------------------------------------
// fp16 tensor-core GEMM via explicit ldmatrix + mma.sync.m16n8k16.
// C[M,N] = epi(A[M,K] @ W[N,K]^T). 128x128 tile, K-tile 64, 2-stage cp.async,
// 8 warps each 32x64.
// ---------------------------------------------------------------------------
#define EPI_NONE    0
#define EPI_SCALE   1
#define EPI_BIAS    2
#define EPI_SIGBIAS 3
#define EPI_RESID   4
#define EPI_SILUMUL 5

#define KTILE 64
#define LDTH 72                    // halves per row (64 + 8 pad) -> 144B stride
#define TILEH (128 * LDTH)
#define CLD 132
#define SMEM_BYTES (4 * TILEH * 2) // 73728 B (>= 128*CLD*4 = 67584)

__device__ __forceinline__ void cpasync16(unsigned saddr, const void* gptr) {
    asm volatile("cp.async.cg.shared.global [%0], [%1], 16;\n"
                 :: "r"(saddr), "l"(gptr));
}
__device__ __forceinline__ void ldsm_x4(unsigned* r, unsigned saddr) {
    asm volatile("ldmatrix.sync.aligned.m8n8.x4.shared.b16 {%0,%1,%2,%3}, [%4];"
                 : "=r"(r[0]), "=r"(r[1]), "=r"(r[2]), "=r"(r[3]) : "r"(saddr));
}
__device__ __forceinline__ void mma16816(
    float* d, const unsigned* a, unsigned b0, unsigned b1)
{
    asm volatile(
        "mma.sync.aligned.m16n8k16.row.col.f32.f16.f16.f32 "
        "{%0,%1,%2,%3}, {%4,%5,%6,%7}, {%8,%9}, {%0,%1,%2,%3};"
        : "+f"(d[0]), "+f"(d[1]), "+f"(d[2]), "+f"(d[3])
        : "r"(a[0]), "r"(a[1]), "r"(a[2]), "r"(a[3]), "r"(b0), "r"(b1));
}

template <int EPI, int HOUT>
__global__ void __launch_bounds__(256, 2) tgemm_kernel(
    const __half* __restrict__ A, const __half* __restrict__ W,
    void* __restrict__ Cout, const float* __restrict__ bias,
    const float* __restrict__ extra,
    int M, int N, int K, float scale)
{
    extern __shared__ __align__(16) char smem_raw[];
    __half* smem = (__half*)smem_raw;
    const int tid  = threadIdx.x;
    const int warp = tid >> 5;
    const int lid  = tid & 31;
    const int wm   = warp & 3;      // 32-row slice
    const int wn   = warp >> 2;     // 64-col slice
    const int bm   = blockIdx.y * 128;
    const int bn   = blockIdx.x * 128;

    __half* Abuf[2] = { smem,             smem + TILEH };
    __half* Bbuf[2] = { smem + 2 * TILEH, smem + 3 * TILEH };
    const unsigned sA[2] = { (unsigned)__cvta_generic_to_shared(Abuf[0]),
                             (unsigned)__cvta_generic_to_shared(Abuf[1]) };
    const unsigned sB[2] = { (unsigned)__cvta_generic_to_shared(Bbuf[0]),
                             (unsigned)__cvta_generic_to_shared(Bbuf[1]) };

    float acc[2][8][4];
    #pragma unroll
    for (int i = 0; i < 2; i++)
        #pragma unroll
        for (int j = 0; j < 8; j++)
            #pragma unroll
            for (int q = 0; q < 4; q++) acc[i][j][q] = 0.0f;

    const int KT = K / KTILE;

    auto load_tile = [&](int kt, int b) {
        const __half* Ag = A + (size_t)bm * K + kt * KTILE;
        const __half* Bg = W + (size_t)bn * K + kt * KTILE;
        #pragma unroll
        for (int j = 0; j < 4; j++) {
            const int i   = tid + (j << 8);
            const int row = i >> 3;
            const int seg = (i & 7) << 3;
            cpasync16(sA[b] + (unsigned)(row * LDTH + seg) * 2,
                      Ag + (size_t)row * K + seg);
            cpasync16(sB[b] + (unsigned)(row * LDTH + seg) * 2,
                      Bg + (size_t)row * K + seg);
        }
    };

    // ldmatrix lane addressing: lanes 0-15 -> rows, lanes 16-31 -> +8 cols
    const int lrow = lid & 15;
    const int lcol = (lid >> 4) << 3;

    load_tile(0, 0);
    asm volatile("cp.async.commit_group;\n");

    int buf = 0;
    for (int kt = 0; kt < KT; kt++) {
        if (kt + 1 < KT) {
            load_tile(kt + 1, buf ^ 1);
            asm volatile("cp.async.commit_group;\n");
            asm volatile("cp.async.wait_group 1;\n");
        } else {
            asm volatile("cp.async.wait_group 0;\n");
        }
        __syncthreads();

        const unsigned As = sA[buf];
        const unsigned Bs = sB[buf];
        #pragma unroll
        for (int kk = 0; kk < 4; kk++) {
            unsigned a[2][4], b[4][4];
            #pragma unroll
            for (int i = 0; i < 2; i++)
                ldsm_x4(a[i], As + (unsigned)((wm * 32 + i * 16 + lrow) * LDTH
                                              + kk * 16 + lcol) * 2);
            #pragma unroll
            for (int j = 0; j < 4; j++)
                ldsm_x4(b[j], Bs + (unsigned)((wn * 64 + j * 16 + lrow) * LDTH
                                              + kk * 16 + lcol) * 2);
            #pragma unroll
            for (int i = 0; i < 2; i++)
                #pragma unroll
                for (int j = 0; j < 4; j++) {
                    mma16816(acc[i][2 * j],     a[i], b[j][0], b[j][2]);
                    mma16816(acc[i][2 * j + 1], a[i], b[j][1], b[j][3]);
                }
        }
        buf ^= 1;
        __syncthreads();
    }

    // stage accumulators to smem for vectorized fused epilogue
    float* Cs = (float*)smem_raw;   // 128 x CLD
    const int tr = lid >> 2;
    const int tc = (lid & 3) << 1;
    #pragma unroll
    for (int i = 0; i < 2; i++)
        #pragma unroll
        for (int j = 0; j < 8; j++) {
            float* p = Cs + (wm * 32 + i * 16 + tr) * CLD + wn * 64 + j * 8 + tc;
            p[0] = acc[i][j][0];
            p[1] = acc[i][j][1];
            p[8 * CLD + 0] = acc[i][j][2];
            p[8 * CLD + 1] = acc[i][j][3];
        }
    __syncthreads();

    #pragma unroll
    for (int it = 0; it < 16; it++) {
        const int idx = tid + (it << 8);
        const int r = idx >> 5;
        const int c = (idx & 31) << 2;
        float4 v4 = *(const float4*)(Cs + r * CLD + c);
        const size_t off = (size_t)(bm + r) * N + bn + c;
        float v[4] = { v4.x, v4.y, v4.z, v4.w };
        #pragma unroll
        for (int q = 0; q < 4; q++) {
            if (EPI == EPI_SCALE) {
                v[q] *= scale;
            } else if (EPI == EPI_BIAS) {
                v[q] += bias[bn + c + q];
            } else if (EPI == EPI_SIGBIAS) {
                v[q] += bias[bn + c + q];
                v[q] = 1.0f / (1.0f + expf(-v[q]));
            } else if (EPI == EPI_RESID) {
                v[q] += extra[off + q];
            } else if (EPI == EPI_SILUMUL) {
                const float g = extra[off + q];
                v[q] *= g / (1.0f + expf(-g));
            }
        }
        if (HOUT) {
            __half2 lo = __floats2half2_rn(v[0], v[1]);
            __half2 hi = __floats2half2_rn(v[2], v[3]);
            uint2 u = { *(unsigned*)&lo, *(unsigned*)&hi };
            *(uint2*)((__half*)Cout + off) = u;
        } else {
            float4 o4 = { v[0], v[1], v[2], v[3] };
            *(float4*)((float*)Cout + off) = o4;
        }
    }
}

// ---------------------------------------------------------------------------
// MinGRU chunked scan (3 passes)
// ---------------------------------------------------------------------------
__global__ void __launch_bounds__(256) scan1_kernel(
    const float* __restrict__ z, const float* __restrict__ ht,
    float* __restrict__ Aout, float* __restrict__ Bout)
{
    const int tid = blockIdx.x * blockDim.x + threadIdx.x;
    const int d = tid & (DD - 1);
    const int r = tid / DD;
    const int c = r & (NC - 1);
    const int b = r / NC;
    const size_t base = ((size_t)b * TT + (size_t)c * CH) * DD + d;
    float Aa = 1.0f, Bb = 0.0f;
    #pragma unroll 4
    for (int t = 0; t < CH; t++) {
        const float zt = z[base + (size_t)t * DD];
        const float hh = ht[base + (size_t)t * DD];
        const float a = 1.0f - zt;
        Bb = a * Bb + zt * hh;
        Aa *= a;
    }
    Aout[tid] = Aa;
    Bout[tid] = Bb;
}

__global__ void __launch_bounds__(256) scan2_kernel(
    const float* __restrict__ h_prev, const float* __restrict__ Ain,
    const float* __restrict__ Bin, float* __restrict__ hstart,
    float* __restrict__ hlast)
{
    const int tid = blockIdx.x * blockDim.x + threadIdx.x;
    if (tid >= BB * DD) return;
    const int d = tid & (DD - 1);
    const int b = tid / DD;
    float h = h_prev[tid];
    for (int c = 0; c < NC; c++) {
        const size_t i = ((size_t)b * NC + c) * DD + d;
        hstart[i] = h;
        h = Ain[i] * h + Bin[i];
    }
    hlast[tid] = h;
}

__global__ void __launch_bounds__(256) scan3_kernel(
    const float* __restrict__ z, const float* __restrict__ ht,
    const float* __restrict__ hstart, float* __restrict__ xout)
{
    const int tid = blockIdx.x * blockDim.x + threadIdx.x;
    const int d = tid & (DD - 1);
    const int r = tid / DD;
    const int c = r & (NC - 1);
    const int b = r / NC;
    const size_t base = ((size_t)b * TT + (size_t)c * CH) * DD + d;
    float h = hstart[tid];
    for (int t = 0; t < CH; t++) {
        const float zt = z[base + (size_t)t * DD];
        const float hh = ht[base + (size_t)t * DD];
        h = (1.0f - zt) * h + zt * hh;
        xout[base + (size_t)t * DD] += h;
    }
}

// ---------------------------------------------------------------------------
// Top-2 over S=4096 scores per row
// ---------------------------------------------------------------------------
__device__ __forceinline__ void top2_insert(float v, int i,
    float& v1, int& i1, float& v2, int& i2)
{
    if (v > v1 || (v == v1 && i < i1)) { v2 = v1; i2 = i1; v1 = v; i1 = i; }
    else if (v > v2 || (v == v2 && i < i2)) { v2 = v; i2 = i; }
}

__global__ void __launch_bounds__(256) top2_kernel(
    const float* __restrict__ scores, float* __restrict__ topv,
    int* __restrict__ topi)
{
    const int row = blockIdx.x;
    const int tid = threadIdx.x;
    const float* sr = scores + (size_t)row * SS;
    float v1 = -3.4e38f, v2 = -3.4e38f;
    int i1 = 0x7fffffff, i2 = 0x7fffffff;
    for (int s = tid; s < SS; s += 256)
        top2_insert(sr[s], s, v1, i1, v2, i2);
    __shared__ float sv1[256], sv2[256];
    __shared__ int si1[256], si2[256];
    sv1[tid] = v1; sv2[tid] = v2; si1[tid] = i1; si2[tid] = i2;
    __syncthreads();
    for (int o = 128; o; o >>= 1) {
        if (tid < o) {
            float a1 = sv1[tid], a2 = sv2[tid];
            int b1 = si1[tid], b2 = si2[tid];
            top2_insert(sv1[tid + o], si1[tid + o], a1, b1, a2, b2);
            top2_insert(sv2[tid + o], si2[tid + o], a1, b1, a2, b2);
            sv1[tid] = a1; sv2[tid] = a2; si1[tid] = b1; si2[tid] = b2;
        }
        __syncthreads();
    }
    if (tid == 0) {
        topv[row * 2 + 0] = sv1[0];
        topv[row * 2 + 1] = sv2[0];
        topi[row * 2 + 0] = si1[0];
        topi[row * 2 + 1] = si2[0];
    }
}

// retrieved -> fp16 out
__global__ void __launch_bounds__(256) gather_kernel(
    const float* __restrict__ topv, const int* __restrict__ topi,
    const float* __restrict__ V, __half* __restrict__ out)
{
    const size_t idx = (size_t)blockIdx.x * blockDim.x + threadIdx.x;
    const int d = (int)(idx & (DD - 1));
    const size_t row = idx / DD;
    const float v1 = topv[row * 2 + 0];
    const float v2 = topv[row * 2 + 1];
    const int i1 = topi[row * 2 + 0];
    const int i2 = topi[row * 2 + 1];
    const float e = expf(v2 - v1);
    const float inv = 1.0f / (1.0f + e);
    const float w1 = inv, w2 = e * inv;
    out[idx] = __float2half_rn(
        w1 * V[(size_t)i1 * DD + d] + w2 * V[(size_t)i2 * DD + d]);
}

// ---------------------------------------------------------------------------
// Launch sequence
// ---------------------------------------------------------------------------
extern "C" void kernel_launch(void* const* d_in, const int* in_sizes, int n_in,
                              void* d_out, int out_size)
{
    (void)in_sizes; (void)n_in; (void)out_size;
    const float* x        = (const float*)d_in[0];
    const float* h_prev   = (const float*)d_in[1];
    const float* norm1_w  = (const float*)d_in[2];
    const float* conv3_w  = (const float*)d_in[3];
    const float* conv7_w  = (const float*)d_in[4];
    const float* conv15_w = (const float*)d_in[5];
    const float* mix_w    = (const float*)d_in[6];
    const float* norm2_w  = (const float*)d_in[7];
    const float* Wz_w     = (const float*)d_in[8];
    const float* Wz_b     = (const float*)d_in[9];
    const float* Wh_w     = (const float*)d_in[10];
    const float* Wh_b     = (const float*)d_in[11];
    const float* norm3_w  = (const float*)d_in[12];
    const float* slot_k   = (const float*)d_in[13];
    const float* slot_v   = (const float*)d_in[14];
    const float* projq_w  = (const float*)d_in[15];
    const float* projout_w= (const float*)d_in[16];
    const float* norm4_w  = (const float*)d_in[17];
    const float* gate_w   = (const float*)d_in[18];
    const float* up_w     = (const float*)d_in[19];
    const float* down_w   = (const float*)d_in[20];
    float* out = (float*)d_out;

    float* scr = nullptr;
    cudaGetSymbolAddress((void**)&scr, g_scratch);
    __half* hp = nullptr;
    cudaGetSymbolAddress((void**)&hp, g_half);

    float* xn    = scr + OFF_XN;
    float* zbuf  = scr + OFF_Z;
    float* htbuf = scr + OFF_HT;
    float* big1  = scr + OFF_BIG1;
    float* scanA = scr + OFF_SA;
    float* scanB = scr + OFF_SB;
    float* hstart= scr + OFF_HS;
    float* topv  = scr + OFF_TV;
    int*   topi  = (int*)(scr + OFF_TI);

    __half* mixh  = hp + HOFF_MIX;
    __half* Wzh   = hp + HOFF_WZ;
    __half* Whh   = hp + HOFF_WH;
    __half* pqh   = hp + HOFF_PQ;
    __half* poh   = hp + HOFF_PO;
    __half* skh   = hp + HOFF_SK;
    __half* gateh = hp + HOFF_GATE;
    __half* uph   = hp + HOFF_UP;
    __half* downh = hp + HOFF_DOWN;
    __half* convh = hp + HOFF_CONVH;
    __half* xnh   = hp + HOFF_XNH;
    __half* big2h = hp + HOFF_BIG2H;

    cudaFuncSetAttribute(tgemm_kernel<EPI_RESID,0>,   cudaFuncAttributeMaxDynamicSharedMemorySize, SMEM_BYTES);
    cudaFuncSetAttribute(tgemm_kernel<EPI_SIGBIAS,0>, cudaFuncAttributeMaxDynamicSharedMemorySize, SMEM_BYTES);
    cudaFuncSetAttribute(tgemm_kernel<EPI_BIAS,0>,    cudaFuncAttributeMaxDynamicSharedMemorySize, SMEM_BYTES);
    cudaFuncSetAttribute(tgemm_kernel<EPI_NONE,1>,    cudaFuncAttributeMaxDynamicSharedMemorySize, SMEM_BYTES);
    cudaFuncSetAttribute(tgemm_kernel<EPI_NONE,0>,    cudaFuncAttributeMaxDynamicSharedMemorySize, SMEM_BYTES);
    cudaFuncSetAttribute(tgemm_kernel<EPI_SCALE,0>,   cudaFuncAttributeMaxDynamicSharedMemorySize, SMEM_BYTES);
    cudaFuncSetAttribute(tgemm_kernel<EPI_SILUMUL,1>, cudaFuncAttributeMaxDynamicSharedMemorySize, SMEM_BYTES);

    const dim3 blk(256);
    const dim3 gD(DD / 128, BT / 128);
    const dim3 gF(FF / 128, BT / 128);
    const dim3 gS(SS / 128, BT / 128);

    // cast weights to fp16
    cast_kernel<<<(unsigned)(MM / 1024), blk>>>(mix_w,    mixh,  MM);
    cast_kernel<<<(unsigned)(MM / 1024), blk>>>(Wz_w,     Wzh,   MM);
    cast_kernel<<<(unsigned)(MM / 1024), blk>>>(Wh_w,     Whh,   MM);
    cast_kernel<<<(unsigned)(MM / 1024), blk>>>(projq_w,  pqh,   MM);
    cast_kernel<<<(unsigned)(MM / 1024), blk>>>(projout_w,poh,   MM);
    cast_kernel<<<(unsigned)(FMsz / 1024), blk>>>(slot_k, skh,   FMsz);
    cast_kernel<<<(unsigned)(FMsz / 1024), blk>>>(gate_w, gateh, FMsz);
    cast_kernel<<<(unsigned)(FMsz / 1024), blk>>>(up_w,   uph,   FMsz);
    cast_kernel<<<(unsigned)(FMsz / 1024), blk>>>(down_w, downh, FMsz);

    // running x lives in d_out
    cudaMemcpyAsync(out, x, BTD * sizeof(float), cudaMemcpyDeviceToDevice);

    // 1. conv block
    rmsnorm_kernel<0><<<BT, blk>>>(out, norm1_w, xn, nullptr);
    conv_kernel<<<(unsigned)(BTD / 256), blk>>>(xn, conv3_w, conv7_w, conv15_w, convh);
    tgemm_kernel<EPI_RESID,0><<<gD, blk, SMEM_BYTES>>>(convh, mixh, out, nullptr, out, BT, DD, DD, 1.0f);

    // 2. MinGRU
    rmsnorm_kernel<1><<<BT, blk>>>(out, norm2_w, nullptr, xnh);
    tgemm_kernel<EPI_SIGBIAS,0><<<gD, blk, SMEM_BYTES>>>(xnh, Wzh, zbuf, Wz_b, nullptr, BT, DD, DD, 1.0f);
    tgemm_kernel<EPI_BIAS,0><<<gD, blk, SMEM_BYTES>>>(xnh, Whh, htbuf, Wh_b, nullptr, BT, DD, DD, 1.0f);
    scan1_kernel<<<(unsigned)(BDNC / 256), blk>>>(zbuf, htbuf, scanA, scanB);
    scan2_kernel<<<(BB * DD + 255) / 256, blk>>>(h_prev, scanA, scanB, hstart, out + BTD);
    scan3_kernel<<<(unsigned)(BDNC / 256), blk>>>(zbuf, htbuf, hstart, out);

    // 3. slot memory
    rmsnorm_kernel<1><<<BT, blk>>>(out, norm3_w, nullptr, xnh);
    tgemm_kernel<EPI_NONE,1><<<gD, blk, SMEM_BYTES>>>(xnh, pqh, convh, nullptr, nullptr, BT, DD, DD, 1.0f);
    tgemm_kernel<EPI_SCALE,0><<<gS, blk, SMEM_BYTES>>>(convh, skh, big1, nullptr, nullptr, BT, SS, DD, 0.03125f);
    top2_kernel<<<BT, blk>>>(big1, topv, topi);
    gather_kernel<<<(unsigned)(BTD / 256), blk>>>(topv, topi, slot_v, xnh);
    tgemm_kernel<EPI_RESID,0><<<gD, blk, SMEM_BYTES>>>(xnh, poh, out, nullptr, out, BT, DD, DD, 1.0f);

    // 4. SwiGLU FFN
    rmsnorm_kernel<1><<<BT, blk>>>(out, norm4_w, nullptr, convh);
    tgemm_kernel<EPI_NONE,0><<<gF, blk, SMEM_BYTES>>>(convh, gateh, big1, nullptr, nullptr, BT, FF, DD, 1.0f);
    tgemm_kernel<EPI_SILUMUL,1><<<gF, blk, SMEM_BYTES>>>(convh, uph, big2h, nullptr, big1, BT, FF, DD, 1.0f);
    tgemm_kernel<EPI_RESID,0><<<gD, blk, SMEM_BYTES>>>(big2h, downh, out, nullptr, out, BT, DD, FF, 1.0f);
}

// round 8
// speedup vs baseline: 5.6371x; 1.0569x over previous
#include <cuda_runtime.h>
#include <cuda_fp16.h>
#include <cstdint>
#include <math.h>

// ---------------------------------------------------------------------------
// Problem constants
// ---------------------------------------------------------------------------
#define BB 2
#define TT 4096
#define DD 1024
#define FF 4096
#define SS 4096
#define BT (BB * TT)          // 8192
#define BTD ((size_t)BT * DD) // 8,388,608
#define BTF ((size_t)BT * FF) // 33,554,432
#define NC 64
#define CH 64
#define BDNC ((size_t)BB * DD * NC) // 131072

#define MM ((size_t)1048576)
#define FMsz (4 * MM)
#define WTOT (21 * MM)        // total weight elements in fp16 pool

// fp32 scratch
__device__ float g_scratch[4 * BTD + 2 * BDNC + BDNC + (size_t)BT * 4 + BTF];

#define OFF_XN   ((size_t)0)
#define OFF_Z    (OFF_XN + BTD)      // zbuf; later reused as top2 candidate vals
#define OFF_HT   (OFF_Z + BTD)       // htbuf; later reused as top2 candidate idx
#define OFF_X1   (OFF_HT + BTD)
#define OFF_SA   (OFF_X1 + BTD)
#define OFF_SB   (OFF_SA + BDNC)
#define OFF_HS   (OFF_SB + BDNC)
#define OFF_TV   (OFF_HS + BDNC)
#define OFF_TI   (OFF_TV + (size_t)BT * 2)

// fp16 pool: weights contiguous (Wz then Wh => fused N=2048 GEMM works in place)
#define HOFF_MIX   ((size_t)0)
#define HOFF_WZ    (1 * MM)
#define HOFF_WH    (2 * MM)
#define HOFF_PQ    (3 * MM)
#define HOFF_PO    (4 * MM)
#define HOFF_SK    (5 * MM)
#define HOFF_GATE  (9 * MM)
#define HOFF_UP    (13 * MM)
#define HOFF_DOWN  (17 * MM)
#define HOFF_CONVH (21 * MM)
#define HOFF_XNH   (HOFF_CONVH + BTD)
#define HOFF_BIG2H (HOFF_XNH + BTD)
__device__ __half g_half[HOFF_BIG2H + BTF];

// ---------------------------------------------------------------------------
// One mega-cast: all 9 weight tensors fp32 -> fp16 pool (layout matches HOFF_*)
// ---------------------------------------------------------------------------
__global__ void __launch_bounds__(256) castall_kernel(
    const float* __restrict__ mix, const float* __restrict__ wz,
    const float* __restrict__ wh,  const float* __restrict__ pq,
    const float* __restrict__ po,  const float* __restrict__ sk,
    const float* __restrict__ gate,const float* __restrict__ up,
    const float* __restrict__ down, __half* __restrict__ dst)
{
    const size_t i = ((size_t)blockIdx.x * blockDim.x + threadIdx.x) * 4;
    if (i >= WTOT) return;
    const float* src; size_t base;
    if (i < 5 * MM) {
        switch (i >> 20) {
            case 0: src = mix; base = 0;      break;
            case 1: src = wz;  base = 1 * MM; break;
            case 2: src = wh;  base = 2 * MM; break;
            case 3: src = pq;  base = 3 * MM; break;
            default: src = po; base = 4 * MM; break;
        }
    } else if (i < 9 * MM)  { src = sk;   base = 5 * MM; }
    else if (i < 13 * MM)   { src = gate; base = 9 * MM; }
    else if (i < 17 * MM)   { src = up;   base = 13 * MM; }
    else                    { src = down; base = 17 * MM; }
    float4 v = *(const float4*)(src + (i - base));
    __half2 lo = __floats2half2_rn(v.x, v.y);
    __half2 hi = __floats2half2_rn(v.z, v.w);
    uint2 o = { *(unsigned*)&lo, *(unsigned*)&hi };
    *(uint2*)(dst + i) = o;
}

// ---------------------------------------------------------------------------
// RMSNorm (fp32 or fp16 out)
// ---------------------------------------------------------------------------
template <int HALF_OUT>
__global__ void __launch_bounds__(256) rmsnorm_kernel(
    const float* __restrict__ x, const float* __restrict__ w,
    float* __restrict__ out, __half* __restrict__ outh)
{
    const size_t row = blockIdx.x;
    const int tid = threadIdx.x;
    const float4* xr = (const float4*)(x + row * DD);
    float4 a = xr[tid];
    float ss = a.x * a.x + a.y * a.y + a.z * a.z + a.w * a.w;
    #pragma unroll
    for (int o = 16; o; o >>= 1) ss += __shfl_xor_sync(0xffffffffu, ss, o);
    __shared__ float wss[8];
    if ((tid & 31) == 0) wss[tid >> 5] = ss;
    __syncthreads();
    if (tid < 8) {
        float v = wss[tid];
        #pragma unroll
        for (int o = 4; o; o >>= 1) v += __shfl_xor_sync(0xffu, v, o);
        if (tid == 0) wss[0] = v;
    }
    __syncthreads();
    const float inv = rsqrtf(wss[0] * (1.0f / DD) + 1e-6f);
    float4 wv = ((const float4*)w)[tid];
    float4 o4;
    o4.x = a.x * wv.x * inv;
    o4.y = a.y * wv.y * inv;
    o4.z = a.z * wv.z * inv;
    o4.w = a.w * wv.w * inv;
    if (HALF_OUT) {
        __half2 lo = __floats2half2_rn(o4.x, o4.y);
        __half2 hi = __floats2half2_rn(o4.z, o4.w);
        uint2 u = { *(unsigned*)&lo, *(unsigned*)&hi };
        *(uint2*)(outh + row * DD + tid * 4) = u;
    } else {
        ((float4*)(out + row * DD))[tid] = o4;
    }
}

// ---------------------------------------------------------------------------
// Multi-scale causal depthwise conv -> fp16 out
// ---------------------------------------------------------------------------
__global__ void __launch_bounds__(256) conv_kernel(
    const float* __restrict__ xn,
    const float* __restrict__ w3, const float* __restrict__ w7,
    const float* __restrict__ w15, __half* __restrict__ out)
{
    const size_t idx = (size_t)blockIdx.x * blockDim.x + threadIdx.x;
    const int d = (int)(idx & (DD - 1));
    const size_t bt = idx / DD;
    const int t = (int)(bt & (TT - 1));
    const int b = (int)(bt / TT);
    const float* base = xn + (size_t)b * TT * DD + d;
    float acc = 0.0f;
    #pragma unroll
    for (int j = 0; j < 15; j++) {
        int tt = t - 14 + j;
        if (tt < 0) continue;
        float wsum = w15[d * 15 + j];
        if (j >= 8)  wsum += w7[d * 7 + (j - 8)];
        if (j >= 12) wsum += w3[d * 3 + (j - 12)];
        acc += wsum * base[(size_t)tt * DD];
    }
    out[idx] = __float2half_rn(acc);
}

// ---------------------------------------------------------------------------
// fp16 tensor GEMM: ldmatrix + mma.sync.m16n8k16, 128x128 tile, K-tile 64,
// 3-stage cp.async pipeline (one __syncthreads per iter), 8 warps 32x64 each.
// Epilogues: RESID / GRU-split / TOP2-reduce / SILUMUL(half) / NONE.
// ---------------------------------------------------------------------------
#define EPI_NONE    0
#define EPI_RESID   4
#define EPI_SILUMUL 5
#define EPI_GRU     6
#define EPI_TOP2    7

#define KTILE 64
#define LDTH 72
#define TILEH (128 * LDTH)                 // halves per tile buffer (A or B)
#define STAGEH (2 * TILEH)                 // halves per stage (A+B)
#define CLD 132
#define SMEM_BYTES (3 * STAGEH * 2)        // 110592 B

__device__ __forceinline__ void cpasync16(unsigned saddr, const void* gptr) {
    asm volatile("cp.async.cg.shared.global [%0], [%1], 16;\n"
                 :: "r"(saddr), "l"(gptr));
}
__device__ __forceinline__ void ldsm_x4(unsigned* r, unsigned saddr) {
    asm volatile("ldmatrix.sync.aligned.m8n8.x4.shared.b16 {%0,%1,%2,%3}, [%4];"
                 : "=r"(r[0]), "=r"(r[1]), "=r"(r[2]), "=r"(r[3]) : "r"(saddr));
}
__device__ __forceinline__ void mma16816(
    float* d, const unsigned* a, unsigned b0, unsigned b1)
{
    asm volatile(
        "mma.sync.aligned.m16n8k16.row.col.f32.f16.f16.f32 "
        "{%0,%1,%2,%3}, {%4,%5,%6,%7}, {%8,%9}, {%0,%1,%2,%3};"
        : "+f"(d[0]), "+f"(d[1]), "+f"(d[2]), "+f"(d[3])
        : "r"(a[0]), "r"(a[1]), "r"(a[2]), "r"(a[3]), "r"(b0), "r"(b1));
}
__device__ __forceinline__ void top2_ins(float v, int i,
    float& v1, int& i1, float& v2, int& i2)
{
    if (v > v1 || (v == v1 && i < i1)) { v2 = v1; i2 = i1; v1 = v; i1 = i; }
    else if (v > v2 || (v == v2 && i < i2)) { v2 = v; i2 = i; }
}

template <int EPI, int HOUT>
__global__ void __launch_bounds__(256, 2) tgemm_kernel(
    const __half* __restrict__ A, const __half* __restrict__ W,
    void* __restrict__ Cout, const float* __restrict__ bias,
    const float* __restrict__ extraf, const __half* __restrict__ extrah,
    float* __restrict__ aux, int* __restrict__ auxi,
    int M, int N, int K, float scale)
{
    extern __shared__ __align__(16) char smem_raw[];
    __half* smem = (__half*)smem_raw;
    const int tid  = threadIdx.x;
    const int warp = tid >> 5;
    const int lid  = tid & 31;
    const int wm   = warp & 3;
    const int wn   = warp >> 2;
    const int bm   = blockIdx.y * 128;
    const int bn   = blockIdx.x * 128;

    unsigned sA[3], sB[3];
    #pragma unroll
    for (int s = 0; s < 3; s++) {
        sA[s] = (unsigned)__cvta_generic_to_shared(smem + s * STAGEH);
        sB[s] = sA[s] + TILEH * 2;
    }

    float acc[2][8][4];
    #pragma unroll
    for (int i = 0; i < 2; i++)
        #pragma unroll
        for (int j = 0; j < 8; j++)
            #pragma unroll
            for (int q = 0; q < 4; q++) acc[i][j][q] = 0.0f;

    const int KT = K / KTILE;

    auto load_tile = [&](int kt, int s) {
        const __half* Ag = A + (size_t)bm * K + kt * KTILE;
        const __half* Bg = W + (size_t)bn * K + kt * KTILE;
        #pragma unroll
        for (int j = 0; j < 4; j++) {
            const int i   = tid + (j << 8);
            const int row = i >> 3;
            const int seg = (i & 7) << 3;
            cpasync16(sA[s] + (unsigned)(row * LDTH + seg) * 2,
                      Ag + (size_t)row * K + seg);
            cpasync16(sB[s] + (unsigned)(row * LDTH + seg) * 2,
                      Bg + (size_t)row * K + seg);
        }
        asm volatile("cp.async.commit_group;\n");
    };

    const int lrow = lid & 15;
    const int lcol = (lid >> 4) << 3;

    load_tile(0, 0);
    load_tile(1, 1);

    for (int kt = 0; kt < KT; kt++) {
        if (kt == KT - 1) asm volatile("cp.async.wait_group 0;\n");
        else              asm volatile("cp.async.wait_group 1;\n");
        __syncthreads();

        const int s = kt % 3;
        const unsigned As = sA[s];
        const unsigned Bs = sB[s];
        #pragma unroll
        for (int kk = 0; kk < 4; kk++) {
            unsigned a[2][4], b[4][4];
            #pragma unroll
            for (int i = 0; i < 2; i++)
                ldsm_x4(a[i], As + (unsigned)((wm * 32 + i * 16 + lrow) * LDTH
                                              + kk * 16 + lcol) * 2);
            #pragma unroll
            for (int j = 0; j < 4; j++)
                ldsm_x4(b[j], Bs + (unsigned)((wn * 64 + j * 16 + lrow) * LDTH
                                              + kk * 16 + lcol) * 2);
            #pragma unroll
            for (int i = 0; i < 2; i++)
                #pragma unroll
                for (int j = 0; j < 4; j++) {
                    mma16816(acc[i][2 * j],     a[i], b[j][0], b[j][2]);
                    mma16816(acc[i][2 * j + 1], a[i], b[j][1], b[j][3]);
                }
        }
        if (kt + 2 < KT) load_tile(kt + 2, (kt + 2) % 3);
    }
    __syncthreads();

    // stage accumulators to smem (reuses pipeline buffers)
    float* Cs = (float*)smem_raw;   // 128 x CLD
    const int tr = lid >> 2;
    const int tc = (lid & 3) << 1;
    #pragma unroll
    for (int i = 0; i < 2; i++)
        #pragma unroll
        for (int j = 0; j < 8; j++) {
            float* p = Cs + (wm * 32 + i * 16 + tr) * CLD + wn * 64 + j * 8 + tc;
            p[0] = acc[i][j][0];
            p[1] = acc[i][j][1];
            p[8 * CLD + 0] = acc[i][j][2];
            p[8 * CLD + 1] = acc[i][j][3];
        }
    __syncthreads();

    // epilogue: warp w handles row (w + 8*it); lanes cover 128 cols as 4 each
    #pragma unroll 1
    for (int it = 0; it < 16; it++) {
        const int idx = tid + (it << 8);
        const int r = idx >> 5;
        const int c = (idx & 31) << 2;
        float4 v4 = *(const float4*)(Cs + r * CLD + c);
        float v[4] = { v4.x, v4.y, v4.z, v4.w };

        if (EPI == EPI_TOP2) {
            // local top2 over this lane's 4 scaled values
            float v1 = -3.4e38f, v2 = -3.4e38f;
            int i1 = 0x7fffffff, i2 = 0x7fffffff;
            #pragma unroll
            for (int q = 0; q < 4; q++)
                top2_ins(v[q] * scale, bn + c + q, v1, i1, v2, i2);
            // warp butterfly top2 reduce
            #pragma unroll
            for (int o = 16; o; o >>= 1) {
                float ov1 = __shfl_xor_sync(0xffffffffu, v1, o);
                float ov2 = __shfl_xor_sync(0xffffffffu, v2, o);
                int   oi1 = __shfl_xor_sync(0xffffffffu, i1, o);
                int   oi2 = __shfl_xor_sync(0xffffffffu, i2, o);
                top2_ins(ov1, oi1, v1, i1, v2, i2);
                top2_ins(ov2, oi2, v1, i1, v2, i2);
            }
            if (lid == 0) {
                const size_t cb = (size_t)(bm + r) * 64 + blockIdx.x * 2;
                aux[cb]  = v1;  aux[cb + 1]  = v2;
                auxi[cb] = i1;  auxi[cb + 1] = i2;
            }
            continue;
        }

        const size_t off = (size_t)(bm + r) * N + bn + c;
        if (EPI == EPI_GRU) {
            const int cg = bn + c;           // 0..2047, CTA stays in one half
            if (cg < DD) {
                float4 bv = *(const float4*)(bias + cg);
                float4 o4;
                o4.x = 1.0f / (1.0f + expf(-(v[0] + bv.x)));
                o4.y = 1.0f / (1.0f + expf(-(v[1] + bv.y)));
                o4.z = 1.0f / (1.0f + expf(-(v[2] + bv.z)));
                o4.w = 1.0f / (1.0f + expf(-(v[3] + bv.w)));
                *(float4*)((float*)Cout + (size_t)(bm + r) * DD + cg) = o4;
            } else {
                float4 bv = *(const float4*)(extraf + cg - DD);
                float4 o4 = { v[0] + bv.x, v[1] + bv.y, v[2] + bv.z, v[3] + bv.w };
                *(float4*)(aux + (size_t)(bm + r) * DD + cg - DD) = o4;
            }
            continue;
        }

        if (EPI == EPI_RESID) {
            float4 ev = *(const float4*)(extraf + off);
            v[0] += ev.x; v[1] += ev.y; v[2] += ev.z; v[3] += ev.w;
        } else if (EPI == EPI_SILUMUL) {
            uint2 eu = *(const uint2*)(extrah + off);
            __half2 e0 = *(__half2*)&eu.x;
            __half2 e1 = *(__half2*)&eu.y;
            float g0 = __low2float(e0), g1 = __high2float(e0);
            float g2 = __low2float(e1), g3 = __high2float(e1);
            v[0] *= g0 / (1.0f + expf(-g0));
            v[1] *= g1 / (1.0f + expf(-g1));
            v[2] *= g2 / (1.0f + expf(-g2));
            v[3] *= g3 / (1.0f + expf(-g3));
        }

        if (HOUT) {
            __half2 lo = __floats2half2_rn(v[0], v[1]);
            __half2 hi = __floats2half2_rn(v[2], v[3]);
            uint2 u = { *(unsigned*)&lo, *(unsigned*)&hi };
            *(uint2*)((__half*)Cout + off) = u;
        } else {
            float4 o4 = { v[0], v[1], v[2], v[3] };
            *(float4*)((float*)Cout + off) = o4;
        }
    }
}

// ---------------------------------------------------------------------------
// Final top-2 over 64 candidates per row -> topv/topi
// ---------------------------------------------------------------------------
__global__ void __launch_bounds__(256) top2final_kernel(
    const float* __restrict__ cval, const int* __restrict__ cidx,
    float* __restrict__ topv, int* __restrict__ topi)
{
    const int row = blockIdx.x * 8 + (threadIdx.x >> 5);
    const int lid = threadIdx.x & 31;
    const size_t base = (size_t)row * 64 + lid * 2;
    float v1 = cval[base], v2 = cval[base + 1];
    int   i1 = cidx[base], i2 = cidx[base + 1];
    if (v2 > v1 || (v2 == v1 && i2 < i1)) {   // normalize pair order
        float tv = v1; v1 = v2; v2 = tv;
        int ti = i1; i1 = i2; i2 = ti;
    }
    #pragma unroll
    for (int o = 16; o; o >>= 1) {
        float ov1 = __shfl_xor_sync(0xffffffffu, v1, o);
        float ov2 = __shfl_xor_sync(0xffffffffu, v2, o);
        int   oi1 = __shfl_xor_sync(0xffffffffu, i1, o);
        int   oi2 = __shfl_xor_sync(0xffffffffu, i2, o);
        top2_ins(ov1, oi1, v1, i1, v2, i2);
        top2_ins(ov2, oi2, v1, i1, v2, i2);
    }
    if (lid == 0) {
        topv[row * 2 + 0] = v1;
        topv[row * 2 + 1] = v2;
        topi[row * 2 + 0] = i1;
        topi[row * 2 + 1] = i2;
    }
}

// ---------------------------------------------------------------------------
// MinGRU chunked scan (3 passes)
// ---------------------------------------------------------------------------
__global__ void __launch_bounds__(256) scan1_kernel(
    const float* __restrict__ z, const float* __restrict__ ht,
    float* __restrict__ Aout, float* __restrict__ Bout)
{
    const int tid = blockIdx.x * blockDim.x + threadIdx.x;
    const int d = tid & (DD - 1);
    const int r = tid / DD;
    const int c = r & (NC - 1);
    const int b = r / NC;
    const size_t base = ((size_t)b * TT + (size_t)c * CH) * DD + d;
    float Aa = 1.0f, Bb = 0.0f;
    #pragma unroll 4
    for (int t = 0; t < CH; t++) {
        const float zt = z[base + (size_t)t * DD];
        const float hh = ht[base + (size_t)t * DD];
        const float a = 1.0f - zt;
        Bb = a * Bb + zt * hh;
        Aa *= a;
    }
    Aout[tid] = Aa;
    Bout[tid] = Bb;
}

__global__ void __launch_bounds__(256) scan2_kernel(
    const float* __restrict__ h_prev, const float* __restrict__ Ain,
    const float* __restrict__ Bin, float* __restrict__ hstart,
    float* __restrict__ hlast)
{
    const int tid = blockIdx.x * blockDim.x + threadIdx.x;
    if (tid >= BB * DD) return;
    const int d = tid & (DD - 1);
    const int b = tid / DD;
    float h = h_prev[tid];
    for (int c = 0; c < NC; c++) {
        const size_t i = ((size_t)b * NC + c) * DD + d;
        hstart[i] = h;
        h = Ain[i] * h + Bin[i];
    }
    hlast[tid] = h;
}

__global__ void __launch_bounds__(256) scan3_kernel(
    const float* __restrict__ z, const float* __restrict__ ht,
    const float* __restrict__ hstart, float* __restrict__ xout)
{
    const int tid = blockIdx.x * blockDim.x + threadIdx.x;
    const int d = tid & (DD - 1);
    const int r = tid / DD;
    const int c = r & (NC - 1);
    const int b = r / NC;
    const size_t base = ((size_t)b * TT + (size_t)c * CH) * DD + d;
    float h = hstart[tid];
    for (int t = 0; t < CH; t++) {
        const float zt = z[base + (size_t)t * DD];
        const float hh = ht[base + (size_t)t * DD];
        h = (1.0f - zt) * h + zt * hh;
        xout[base + (size_t)t * DD] += h;
    }
}

// retrieved -> fp16 out
__global__ void __launch_bounds__(256) gather_kernel(
    const float* __restrict__ topv, const int* __restrict__ topi,
    const float* __restrict__ V, __half* __restrict__ out)
{
    const size_t idx = (size_t)blockIdx.x * blockDim.x + threadIdx.x;
    const int d = (int)(idx & (DD - 1));
    const size_t row = idx / DD;
    const float v1 = topv[row * 2 + 0];
    const float v2 = topv[row * 2 + 1];
    const int i1 = topi[row * 2 + 0];
    const int i2 = topi[row * 2 + 1];
    const float e = expf(v2 - v1);
    const float inv = 1.0f / (1.0f + e);
    const float w1 = inv, w2 = e * inv;
    out[idx] = __float2half_rn(
        w1 * V[(size_t)i1 * DD + d] + w2 * V[(size_t)i2 * DD + d]);
}

// ---------------------------------------------------------------------------
// Launch sequence
// ---------------------------------------------------------------------------
extern "C" void kernel_launch(void* const* d_in, const int* in_sizes, int n_in,
                              void* d_out, int out_size)
{
    (void)in_sizes; (void)n_in; (void)out_size;
    const float* x        = (const float*)d_in[0];
    const float* h_prev   = (const float*)d_in[1];
    const float* norm1_w  = (const float*)d_in[2];
    const float* conv3_w  = (const float*)d_in[3];
    const float* conv7_w  = (const float*)d_in[4];
    const float* conv15_w = (const float*)d_in[5];
    const float* mix_w    = (const float*)d_in[6];
    const float* norm2_w  = (const float*)d_in[7];
    const float* Wz_w     = (const float*)d_in[8];
    const float* Wz_b     = (const float*)d_in[9];
    const float* Wh_w     = (const float*)d_in[10];
    const float* Wh_b     = (const float*)d_in[11];
    const float* norm3_w  = (const float*)d_in[12];
    const float* slot_k   = (const float*)d_in[13];
    const float* slot_v   = (const float*)d_in[14];
    const float* projq_w  = (const float*)d_in[15];
    const float* projout_w= (const float*)d_in[16];
    const float* norm4_w  = (const float*)d_in[17];
    const float* gate_w   = (const float*)d_in[18];
    const float* up_w     = (const float*)d_in[19];
    const float* down_w   = (const float*)d_in[20];
    float* out = (float*)d_out;

    float* scr = nullptr;
    cudaGetSymbolAddress((void**)&scr, g_scratch);
    __half* hp = nullptr;
    cudaGetSymbolAddress((void**)&hp, g_half);

    float* xn    = scr + OFF_XN;
    float* zbuf  = scr + OFF_Z;      // also top2 candidate vals
    float* htbuf = scr + OFF_HT;     // also top2 candidate idx
    float* scanA = scr + OFF_SA;
    float* scanB = scr + OFF_SB;
    float* hstart= scr + OFF_HS;
    float* topv  = scr + OFF_TV;
    int*   topi  = (int*)(scr + OFF_TI);

    __half* mixh  = hp + HOFF_MIX;
    __half* Wzh   = hp + HOFF_WZ;    // Wz||Wh contiguous => fused N=2048
    __half* pqh   = hp + HOFF_PQ;
    __half* poh   = hp + HOFF_PO;
    __half* skh   = hp + HOFF_SK;
    __half* gateh = hp + HOFF_GATE;
    __half* uph   = hp + HOFF_UP;
    __half* downh = hp + HOFF_DOWN;
    __half* convh = hp + HOFF_CONVH;
    __half* xnh   = hp + HOFF_XNH;
    __half* big2h = hp + HOFF_BIG2H;

    cudaFuncSetAttribute(tgemm_kernel<EPI_RESID,0>,   cudaFuncAttributeMaxDynamicSharedMemorySize, SMEM_BYTES);
    cudaFuncSetAttribute(tgemm_kernel<EPI_GRU,0>,     cudaFuncAttributeMaxDynamicSharedMemorySize, SMEM_BYTES);
    cudaFuncSetAttribute(tgemm_kernel<EPI_NONE,1>,    cudaFuncAttributeMaxDynamicSharedMemorySize, SMEM_BYTES);
    cudaFuncSetAttribute(tgemm_kernel<EPI_TOP2,0>,    cudaFuncAttributeMaxDynamicSharedMemorySize, SMEM_BYTES);
    cudaFuncSetAttribute(tgemm_kernel<EPI_SILUMUL,1>, cudaFuncAttributeMaxDynamicSharedMemorySize, SMEM_BYTES);

    const dim3 blk(256);
    const dim3 gD(DD / 128, BT / 128);     // 8 x 64
    const dim3 gG(2048 / 128, BT / 128);   // fused GRU GEMM
    const dim3 gF(FF / 128, BT / 128);     // 32 x 64
    const dim3 gS(SS / 128, BT / 128);

    // one mega-cast for all weights
    castall_kernel<<<(unsigned)(WTOT / 1024), blk>>>(
        mix_w, Wz_w, Wh_w, projq_w, projout_w, slot_k, gate_w, up_w, down_w, hp);

    // 1. conv block (residual reads x directly; no pre-copy of x into out)
    rmsnorm_kernel<0><<<BT, blk>>>(x, norm1_w, xn, nullptr);
    conv_kernel<<<(unsigned)(BTD / 256), blk>>>(xn, conv3_w, conv7_w, conv15_w, convh);
    tgemm_kernel<EPI_RESID,0><<<gD, blk, SMEM_BYTES>>>(
        convh, mixh, out, nullptr, x, nullptr, nullptr, nullptr, BT, DD, DD, 1.0f);

    // 2. MinGRU (fused Wz+Wh GEMM)
    rmsnorm_kernel<1><<<BT, blk>>>(out, norm2_w, nullptr, xnh);
    tgemm_kernel<EPI_GRU,0><<<gG, blk, SMEM_BYTES>>>(
        xnh, Wzh, zbuf, Wz_b, Wh_b, nullptr, htbuf, nullptr, BT, 2048, DD, 1.0f);
    scan1_kernel<<<(unsigned)(BDNC / 256), blk>>>(zbuf, htbuf, scanA, scanB);
    scan2_kernel<<<(BB * DD + 255) / 256, blk>>>(h_prev, scanA, scanB, hstart, out + BTD);
    scan3_kernel<<<(unsigned)(BDNC / 256), blk>>>(zbuf, htbuf, hstart, out);

    // 3. slot memory (top2 fused into scores GEMM epilogue; scores never stored)
    rmsnorm_kernel<1><<<BT, blk>>>(out, norm3_w, nullptr, xnh);
    tgemm_kernel<EPI_NONE,1><<<gD, blk, SMEM_BYTES>>>(
        xnh, pqh, convh, nullptr, nullptr, nullptr, nullptr, nullptr, BT, DD, DD, 1.0f);
    tgemm_kernel<EPI_TOP2,0><<<gS, blk, SMEM_BYTES>>>(
        convh, skh, nullptr, nullptr, nullptr, nullptr, zbuf, (int*)htbuf,
        BT, SS, DD, 0.03125f);
    top2final_kernel<<<BT / 8, blk>>>(zbuf, (int*)htbuf, topv, topi);
    gather_kernel<<<(unsigned)(BTD / 256), blk>>>(topv, topi, slot_v, xnh);
    tgemm_kernel<EPI_RESID,0><<<gD, blk, SMEM_BYTES>>>(
        xnh, poh, out, nullptr, out, nullptr, nullptr, nullptr, BT, DD, DD, 1.0f);

    // 4. SwiGLU FFN (gate preact fp16; swiglu in-place in big2h)
    rmsnorm_kernel<1><<<BT, blk>>>(out, norm4_w, nullptr, convh);
    tgemm_kernel<EPI_NONE,1><<<gF, blk, SMEM_BYTES>>>(
        convh, gateh, big2h, nullptr, nullptr, nullptr, nullptr, nullptr, BT, FF, DD, 1.0f);
    tgemm_kernel<EPI_SILUMUL,1><<<gF, blk, SMEM_BYTES>>>(
        convh, uph, big2h, nullptr, nullptr, big2h, nullptr, nullptr, BT, FF, DD, 1.0f);
    tgemm_kernel<EPI_RESID,0><<<gD, blk, SMEM_BYTES>>>(
        big2h, downh, out, nullptr, out, nullptr, nullptr, nullptr, BT, DD, FF, 1.0f);
}